// round 15
// baseline (speedup 1.0000x reference)
#include <cuda_runtime.h>
#include <cuda_fp16.h>
#include <math.h>
#include <stdint.h>

#define NN 50000
#define NE 800000
#define INF 128
#define HIDF 256
#define OUTF 128
#define KN1 384
#define TBK 16
#define TBK2 32

// tf32 helper strides (pre/n1)
#define BS_STRIDE 264
#define AS_STRIDE 36

// fused f16 kernel SMEM layout (u32 units) -- 128-edge tile
#define MS_STR 132            // 128 u32 (256 halves) + 4 pad (132 % 32 == 4)
#define AS_STR 20
#define BS_STR 20
#define U_MS 0                // 128*132 = 16896 (phase-1 As aliases head: 128*20=2560)
#define U_BS 16896            // 2 bufs x 256 rows x 20 = 10240
#define U_F  27136
#define U_WR   (U_F)
#define U_B1   (U_F + 256)
#define U_B2   (U_F + 512)
#define U_BC1  (U_F + 768)
#define U_W2   (U_F + 1024)
#define U_RAD  (U_F + 1280)
#define U_RED  (U_F + 1408)
#define U_SRC  (U_F + 1536)
#define U_DST  (U_F + 1664)
#define E2C_SMEM_BYTES ((U_F + 1792) * 4)   // 115712

typedef unsigned long long u64;

__device__ __forceinline__ float silu_f(float x) {
    return x * (1.0f / (1.0f + __expf(-x)));
}

// ---- packed f32x2 helpers (fp32 k_n2) ----
__device__ __forceinline__ u64 pk2(float lo, float hi) {
    u64 r; asm("mov.b64 %0, {%1, %2};" : "=l"(r) : "f"(lo), "f"(hi)); return r;
}
__device__ __forceinline__ u64 pkb(float x) {
    u64 r; asm("mov.b64 %0, {%1, %1};" : "=l"(r) : "f"(x)); return r;
}
__device__ __forceinline__ void upk2(u64 v, float& lo, float& hi) {
    asm("mov.b64 {%0, %1}, %2;" : "=f"(lo), "=f"(hi) : "l"(v));
}
__device__ __forceinline__ void fma2(u64& acc, u64 a, u64 b) {
    asm("fma.rn.f32x2 %0, %1, %2, %0;" : "+l"(acc) : "l"(a), "l"(b));
}
__device__ __forceinline__ void mt_step(u64 (&acc2)[8][4], const float* __restrict__ Arow,
                                        const float* __restrict__ Brow, int ty8, int tx8) {
    float4 a0 = *(const float4*)(Arow + ty8);
    float4 a1 = *(const float4*)(Arow + ty8 + 4);
    float4 b0 = *(const float4*)(Brow + tx8);
    float4 b1 = *(const float4*)(Brow + tx8 + 4);
    float ar[8] = {a0.x, a0.y, a0.z, a0.w, a1.x, a1.y, a1.z, a1.w};
    u64 br2[4] = {pk2(b0.x, b0.y), pk2(b0.z, b0.w), pk2(b1.x, b1.y), pk2(b1.z, b1.w)};
#pragma unroll
    for (int i = 0; i < 8; i++) {
        u64 aa = pkb(ar[i]);
#pragma unroll
        for (int jp = 0; jp < 4; jp++) fma2(acc2[i][jp], aa, br2[jp]);
    }
}

// ---- tf32 mma (pre/n1) ----
__device__ __forceinline__ uint32_t f2tf(float x) {
    uint32_t r; asm("cvt.rna.tf32.f32 %0, %1;" : "=r"(r) : "f"(x)); return r;
}
__device__ __forceinline__ void mma_tf32(float (&c)[4], const uint32_t (&a)[4],
                                         const uint32_t (&b)[2]) {
    asm("mma.sync.aligned.m16n8k8.row.col.f32.tf32.tf32.f32 "
        "{%0,%1,%2,%3}, {%4,%5,%6,%7}, {%8,%9}, {%0,%1,%2,%3};"
        : "+f"(c[0]), "+f"(c[1]), "+f"(c[2]), "+f"(c[3])
        : "r"(a[0]), "r"(a[1]), "r"(a[2]), "r"(a[3]), "r"(b[0]), "r"(b[1]));
}

// ---- f16 mma m16n8k16 ----
__device__ __forceinline__ void mma_f16(float (&c)[4], const uint32_t (&a)[4],
                                        const uint32_t (&b)[2]) {
    asm("mma.sync.aligned.m16n8k16.row.col.f32.f16.f16.f32 "
        "{%0,%1,%2,%3}, {%4,%5,%6,%7}, {%8,%9}, {%0,%1,%2,%3};"
        : "+f"(c[0]), "+f"(c[1]), "+f"(c[2]), "+f"(c[3])
        : "r"(a[0]), "r"(a[1]), "r"(a[2]), "r"(a[3]), "r"(b[0]), "r"(b[1]));
}

__device__ __forceinline__ uint32_t h2u(float lo, float hi) {
    __half2 h = __floats2half2_rn(lo, hi);
    return *(uint32_t*)&h;
}

__device__ __forceinline__ void red_v2(float* p, float a, float b) {
    asm volatile("red.global.add.v2.f32 [%0], {%1, %2};"
                 :: "l"(p), "f"(a), "f"(b) : "memory");
}
__device__ __forceinline__ void cp16(uint32_t s_addr, const void* g) {
    asm volatile("cp.async.cg.shared.global [%0], [%1], 16;" :: "r"(s_addr), "l"(g));
}
#define CP_COMMIT() asm volatile("cp.async.commit_group;")
template <int N>
__device__ __forceinline__ void cp_wait() {
    asm volatile("cp.async.wait_group %0;" :: "n"(N));
}

// ---------------- scratch ----------------
__device__ float g_xdiff[NE * 4];
__device__ float g_pa[(size_t)NN * HIDF];
__device__ float g_pb[(size_t)NN * HIDF];
__device__ float g_hneigh[(size_t)NN * HIDF];
__device__ float g_xsum[NN * 3];
__device__ float g_deg[NN];
__device__ float g_hn1[(size_t)NN * HIDF];
__device__ float g_colsum[OUTF];
__device__ float g_colsq[OUTF];
__device__ uint32_t g_wt_e1[2 * INF * HIDF];     // tf32
__device__ uint32_t g_wt_n1[KN1 * HIDF];         // tf32
__device__ uint32_t g_wth_e2[HIDF * HIDF / 2];   // half, transposed [n][k]
__device__ uint32_t g_wth_c1[HIDF * HIDF / 2];   // half, transposed [n][k]

// ---------------- weight preps ----------------
__global__ void k_cvtw(const float* __restrict__ We1, const float* __restrict__ Wn1) {
    int i = blockIdx.x * blockDim.x + threadIdx.x;
    if (i < 2 * INF * HIDF) g_wt_e1[i] = f2tf(We1[i]);
    if (i < KN1 * HIDF) g_wt_n1[i] = f2tf(Wn1[i]);
}
__global__ void k_wth(const float* __restrict__ We2, const float* __restrict__ Wc1) {
    int i = blockIdx.x * blockDim.x + threadIdx.x;
    if (i >= HIDF * HIDF) return;
    int k = i >> 8, n = i & 255;
    ((__half*)g_wth_e2)[n * 256 + k] = __float2half(We2[i]);
    ((__half*)g_wth_c1)[n * 256 + k] = __float2half(Wc1[i]);
}

// ---------------- edge geometry ----------------
__global__ void k_geom(const float* __restrict__ coord,
                       const int* __restrict__ src,
                       const int* __restrict__ dst) {
    int e = blockIdx.x * blockDim.x + threadIdx.x;
    if (e >= NE) return;
    int s = src[e], d = dst[e];
    float ax = coord[s * 3 + 0], ay = coord[s * 3 + 1], az = coord[s * 3 + 2];
    float bx = coord[d * 3 + 0], by = coord[d * 3 + 1], bz = coord[d * 3 + 2];
    float dx = ax - bx, dy = ay - by, dz = az - bz;
    float r = dx * dx + dy * dy + dz * dz;
    float inv = 1.0f / (sqrtf(r) + 1e-30f);
    ((float4*)g_xdiff)[e] = make_float4(dx * inv, dy * inv, dz * inv, r);
    atomicAdd(&g_deg[d], 1.0f);
}

// ---------------- node pre-GEMM (tf32) ----------------
__global__ __launch_bounds__(512, 2)
void k_pre_tf(const float* __restrict__ nf) {
    __shared__ uint32_t As[64][AS_STRIDE];
    __shared__ uint32_t Bs[TBK2][BS_STRIDE];
    const int tid = threadIdx.x;
    const int row0 = blockIdx.x * 64;
    const int z = blockIdx.y;
    float* out = z ? g_pb : g_pa;
    const uint32_t bs_base = (uint32_t)__cvta_generic_to_shared(&Bs[0][0]);
    const int lane = tid & 31;
    const int g = lane >> 2;
    const int tig = lane & 3;
    const int wid = tid >> 5;
    const int wr = wid >> 3;
    const int wc = wid & 7;
    float c[2][4][4];
#pragma unroll
    for (int mt = 0; mt < 2; mt++)
#pragma unroll
        for (int nt = 0; nt < 4; nt++)
#pragma unroll
            for (int q = 0; q < 4; q++) c[mt][nt][q] = 0.0f;

    for (int kt = 0; kt < INF / TBK2; kt++) {
#pragma unroll
        for (int i = 0; i < 4; i++) {
            int f = tid + i * 512;
            int kk = f >> 6;
            int cc = (f & 63) << 2;
            cp16(bs_base + (uint32_t)(kk * BS_STRIDE + cc) * 4,
                 g_wt_e1 + (size_t)(z * INF + kt * TBK2 + kk) * HIDF + cc);
        }
        {
            int r = tid >> 3;
            int kk = (tid & 7) << 2;
            int rr = min(row0 + r, NN - 1);
            float4 v = *(const float4*)(nf + (size_t)rr * INF + kt * TBK2 + kk);
            uint4 o;
            o.x = f2tf(v.x); o.y = f2tf(v.y); o.z = f2tf(v.z); o.w = f2tf(v.w);
            *(uint4*)&As[r][kk] = o;
        }
        CP_COMMIT();
        cp_wait<0>();
        __syncthreads();
#pragma unroll
        for (int ks = 0; ks < TBK2; ks += 8) {
            uint32_t af[2][4], bf[4][2];
#pragma unroll
            for (int mt = 0; mt < 2; mt++) {
                int rb = wr * 32 + mt * 16;
                af[mt][0] = As[rb + g][ks + tig];
                af[mt][1] = As[rb + g + 8][ks + tig];
                af[mt][2] = As[rb + g][ks + tig + 4];
                af[mt][3] = As[rb + g + 8][ks + tig + 4];
            }
#pragma unroll
            for (int nt = 0; nt < 4; nt++) {
                int cb = wc * 32 + nt * 8;
                bf[nt][0] = Bs[ks + tig][cb + g];
                bf[nt][1] = Bs[ks + tig + 4][cb + g];
            }
#pragma unroll
            for (int mt = 0; mt < 2; mt++)
#pragma unroll
                for (int nt = 0; nt < 4; nt++)
                    mma_tf32(c[mt][nt], af[mt], bf[nt]);
        }
        __syncthreads();
    }
#pragma unroll
    for (int mt = 0; mt < 2; mt++) {
        int r1 = row0 + wr * 32 + mt * 16 + g;
        int r2 = r1 + 8;
#pragma unroll
        for (int nt = 0; nt < 4; nt++) {
            int lc = wc * 32 + nt * 8 + tig * 2;
            if (r1 < NN)
                *(float2*)(out + (size_t)r1 * HIDF + lc) =
                    make_float2(c[mt][nt][0], c[mt][nt][1]);
            if (r2 < NN)
                *(float2*)(out + (size_t)r2 * HIDF + lc) =
                    make_float2(c[mt][nt][2], c[mt][nt][3]);
        }
    }
}

// ---------------- FUSED edge kernel (f16 m16n8k16, 128-edge tile, 1024 thr) ----------------
__global__ __launch_bounds__(1024, 1)
void k_e2c(const int* __restrict__ src, const int* __restrict__ dst,
           const float* __restrict__ W1row, const float* __restrict__ b1,
           const float* __restrict__ b2, const float* __restrict__ bc1,
           const float* __restrict__ Wc2) {
    extern __shared__ uint32_t sm[];
    uint32_t* sm_ms = sm + U_MS;        // msg_h half tile, 128 x MS_STR
    uint32_t* sm_as = sm + U_MS;        // phase-1 gather chunk (aliases head)
    uint32_t* sm_bs = sm + U_BS;        // B half chunks, 2 x 256 x BS_STR
    float* s_wr  = (float*)(sm + U_WR);
    float* s_b1  = (float*)(sm + U_B1);
    float* s_b2  = (float*)(sm + U_B2);
    float* s_bc1 = (float*)(sm + U_BC1);
    float* s_w2  = (float*)(sm + U_W2);
    float* s_rad = (float*)(sm + U_RAD);
    float* s_red = (float*)(sm + U_RED);
    int*   s_src = (int*)(sm + U_SRC);
    int*   s_dst = (int*)(sm + U_DST);

    const int tid = threadIdx.x;
    const int row0 = blockIdx.x * 128;
    if (tid < 128) {
        int e = row0 + tid;
        s_src[tid] = src[e];
        s_dst[tid] = dst[e];
        s_rad[tid] = g_xdiff[e * 4 + 3];
        s_red[tid] = 0.0f;
    }
    if (tid >= 512 && tid < 512 + HIDF) {
        int t = tid - 512;
        s_wr[t] = W1row[t];
        s_b1[t] = b1[t];
        s_b2[t] = b2[t];
        s_bc1[t] = bc1[t];
        s_w2[t] = Wc2[t];
    }
    __syncthreads();
    const uint32_t bs_base = (uint32_t)__cvta_generic_to_shared(sm_bs);
    const int lane = tid & 31;
    const int g = lane >> 2;
    const int tig = lane & 3;
    const int wid = tid >> 5;
    const int wr = wid >> 3;   // 0..3 -> 32 rows each
    const int wc = wid & 7;    // 0..7 -> 32 cols each
    float c[2][4][4];
#pragma unroll
    for (int mt = 0; mt < 2; mt++)
#pragma unroll
        for (int nt = 0; nt < 4; nt++)
#pragma unroll
            for (int q = 0; q < 4; q++) c[mt][nt][q] = 0.0f;

    // B chunk: 256 n-rows x 16 u32 = 1024 cp16, 1/thread
#define ISSUE_B(WTH, KB, BUF)                                                    \
    {                                                                            \
        int n = tid >> 2;                                                        \
        int j = (tid & 3) << 2;                                                  \
        cp16(bs_base + (uint32_t)(((BUF) * 256 + n) * BS_STR + j) * 4,           \
             (WTH) + (size_t)n * 128 + (KB) * 16 + j);                           \
    }

    // ================= phase 1: msg_h = silu(A @ W_e2 + b2) =================
    ISSUE_B(g_wth_e2, 0, 0);
    CP_COMMIT();
    for (int kb = 0; kb < 8; kb++) {     // K chunks of 32
        const int buf = kb & 1;
        // A staging: 128 rows x 32 halves; thread -> 4 halves (uint2)
        {
            int r = tid >> 3;
            int k4 = (tid & 7) << 2;
            int kg = kb * 32 + k4;
            float4 va = *(const float4*)(g_pa + (size_t)s_src[r] * HIDF + kg);
            float4 vb = *(const float4*)(g_pb + (size_t)s_dst[r] * HIDF + kg);
            float rad = s_rad[r];
            float v0 = silu_f(va.x + vb.x + rad * s_wr[kg + 0] + s_b1[kg + 0]);
            float v1 = silu_f(va.y + vb.y + rad * s_wr[kg + 1] + s_b1[kg + 1]);
            float v2 = silu_f(va.z + vb.z + rad * s_wr[kg + 2] + s_b1[kg + 2]);
            float v3 = silu_f(va.w + vb.w + rad * s_wr[kg + 3] + s_b1[kg + 3]);
            *(uint2*)&sm_as[r * AS_STR + ((tid & 7) << 1)] =
                make_uint2(h2u(v0, v1), h2u(v2, v3));
        }
        if (kb + 1 < 8) {
            ISSUE_B(g_wth_e2, kb + 1, buf ^ 1);
            CP_COMMIT();
            cp_wait<1>();
        } else {
            cp_wait<0>();
        }
        __syncthreads();
#pragma unroll
        for (int ks = 0; ks < 2; ks++) {
            const int kb2 = ks * 8;
            uint32_t af[2][4], bf[4][2];
#pragma unroll
            for (int mt = 0; mt < 2; mt++) {
                int rb = wr * 32 + mt * 16;
                af[mt][0] = sm_as[(rb + g) * AS_STR + kb2 + tig];
                af[mt][1] = sm_as[(rb + g + 8) * AS_STR + kb2 + tig];
                af[mt][2] = sm_as[(rb + g) * AS_STR + kb2 + tig + 4];
                af[mt][3] = sm_as[(rb + g + 8) * AS_STR + kb2 + tig + 4];
            }
#pragma unroll
            for (int nt = 0; nt < 4; nt++) {
                int cb = wc * 32 + nt * 8;
                bf[nt][0] = sm_bs[(buf * 256 + cb + g) * BS_STR + kb2 + tig];
                bf[nt][1] = sm_bs[(buf * 256 + cb + g) * BS_STR + kb2 + tig + 4];
            }
#pragma unroll
            for (int mt = 0; mt < 2; mt++)
#pragma unroll
                for (int nt = 0; nt < 4; nt++)
                    mma_f16(c[mt][nt], af[mt], bf[nt]);
        }
        __syncthreads();
    }
    // ---- epilogue 1: bias+silu, stash msg_h as half, h_neigh reduce ----
#pragma unroll
    for (int mt = 0; mt < 2; mt++) {
        int r1 = wr * 32 + mt * 16 + g;
        int r2 = r1 + 8;
        int d1 = s_dst[r1], d2 = s_dst[r2];
#pragma unroll
        for (int nt = 0; nt < 4; nt++) {
            int lc = wc * 32 + nt * 8 + tig * 2;
            float v0 = silu_f(c[mt][nt][0] + s_b2[lc]);
            float v1 = silu_f(c[mt][nt][1] + s_b2[lc + 1]);
            float v2 = silu_f(c[mt][nt][2] + s_b2[lc]);
            float v3 = silu_f(c[mt][nt][3] + s_b2[lc + 1]);
            sm_ms[r1 * MS_STR + (lc >> 1)] = h2u(v0, v1);
            sm_ms[r2 * MS_STR + (lc >> 1)] = h2u(v2, v3);
            red_v2(g_hneigh + (size_t)d1 * HIDF + lc, v0, v1);
            red_v2(g_hneigh + (size_t)d2 * HIDF + lc, v2, v3);
        }
    }
    __syncthreads();

    // ================= phase 2: t = msg_h @ W_c1 (A resident as half) =================
#pragma unroll
    for (int mt = 0; mt < 2; mt++)
#pragma unroll
        for (int nt = 0; nt < 4; nt++)
#pragma unroll
            for (int q = 0; q < 4; q++) c[mt][nt][q] = 0.0f;

    ISSUE_B(g_wth_c1, 0, 0);
    CP_COMMIT();
    for (int kb = 0; kb < 8; kb++) {
        const int buf = kb & 1;
        if (kb + 1 < 8) {
            ISSUE_B(g_wth_c1, kb + 1, buf ^ 1);
            CP_COMMIT();
            cp_wait<1>();
        } else {
            cp_wait<0>();
        }
        __syncthreads();
#pragma unroll
        for (int ks = 0; ks < 2; ks++) {
            const int ku = kb * 16 + ks * 8;
            const int kb2 = ks * 8;
            uint32_t af[2][4], bf[4][2];
#pragma unroll
            for (int mt = 0; mt < 2; mt++) {
                int rb = wr * 32 + mt * 16;
                af[mt][0] = sm_ms[(rb + g) * MS_STR + ku + tig];
                af[mt][1] = sm_ms[(rb + g + 8) * MS_STR + ku + tig];
                af[mt][2] = sm_ms[(rb + g) * MS_STR + ku + tig + 4];
                af[mt][3] = sm_ms[(rb + g + 8) * MS_STR + ku + tig + 4];
            }
#pragma unroll
            for (int nt = 0; nt < 4; nt++) {
                int cb = wc * 32 + nt * 8;
                bf[nt][0] = sm_bs[(buf * 256 + cb + g) * BS_STR + kb2 + tig];
                bf[nt][1] = sm_bs[(buf * 256 + cb + g) * BS_STR + kb2 + tig + 4];
            }
#pragma unroll
            for (int mt = 0; mt < 2; mt++)
#pragma unroll
                for (int nt = 0; nt < 4; nt++)
                    mma_f16(c[mt][nt], af[mt], bf[nt]);
        }
        __syncthreads();
    }
    // ---- epilogue 2: s = sum silu(t+bc1)*w2 ; scatter x_sum ----
#pragma unroll
    for (int mt = 0; mt < 2; mt++) {
        float s1 = 0.0f, s2 = 0.0f;
#pragma unroll
        for (int nt = 0; nt < 4; nt++) {
            int lc = wc * 32 + nt * 8 + tig * 2;
            s1 += silu_f(c[mt][nt][0] + s_bc1[lc]) * s_w2[lc]
                + silu_f(c[mt][nt][1] + s_bc1[lc + 1]) * s_w2[lc + 1];
            s2 += silu_f(c[mt][nt][2] + s_bc1[lc]) * s_w2[lc]
                + silu_f(c[mt][nt][3] + s_bc1[lc + 1]) * s_w2[lc + 1];
        }
        s1 += __shfl_xor_sync(0xffffffffu, s1, 1);
        s1 += __shfl_xor_sync(0xffffffffu, s1, 2);
        s2 += __shfl_xor_sync(0xffffffffu, s2, 1);
        s2 += __shfl_xor_sync(0xffffffffu, s2, 2);
        if (tig == 0) {
            atomicAdd(&s_red[wr * 32 + mt * 16 + g], s1);
            atomicAdd(&s_red[wr * 32 + mt * 16 + g + 8], s2);
        }
    }
    __syncthreads();
    if (tid < 128) {
        int e = row0 + tid;
        float s = s_red[tid];
        float4 xd = *(const float4*)(g_xdiff + (size_t)e * 4);
        int d = s_dst[tid];
        atomicAdd(&g_xsum[d * 3 + 0], s * xd.x);
        atomicAdd(&g_xsum[d * 3 + 1], s * xd.y);
        atomicAdd(&g_xsum[d * 3 + 2], s * xd.z);
    }
#undef ISSUE_B
}

// ---------------- node GEMM 1 (tf32) ----------------
__global__ __launch_bounds__(512, 2)
void k_n1_tf(const float* __restrict__ nf, const float* __restrict__ b) {
    __shared__ uint32_t As[64][AS_STRIDE];
    __shared__ uint32_t Bs[TBK2][BS_STRIDE];
    __shared__ float s_b[HIDF];
    const int tid = threadIdx.x;
    const int row0 = blockIdx.x * 64;
    if (tid < HIDF) s_b[tid] = b[tid];
    const uint32_t bs_base = (uint32_t)__cvta_generic_to_shared(&Bs[0][0]);
    const int lane = tid & 31;
    const int g = lane >> 2;
    const int tig = lane & 3;
    const int wid = tid >> 5;
    const int wr = wid >> 3;
    const int wc = wid & 7;
    float c[2][4][4];
#pragma unroll
    for (int mt = 0; mt < 2; mt++)
#pragma unroll
        for (int nt = 0; nt < 4; nt++)
#pragma unroll
            for (int q = 0; q < 4; q++) c[mt][nt][q] = 0.0f;
    __syncthreads();

    for (int kt = 0; kt < KN1 / TBK2; kt++) {
#pragma unroll
        for (int i = 0; i < 4; i++) {
            int f = tid + i * 512;
            int kk = f >> 6;
            int cc = (f & 63) << 2;
            cp16(bs_base + (uint32_t)(kk * BS_STRIDE + cc) * 4,
                 g_wt_n1 + (size_t)(kt * TBK2 + kk) * HIDF + cc);
        }
        {
            int r = tid >> 3;
            int kk = (tid & 7) << 2;
            int kg = kt * TBK2 + kk;
            int rr = min(row0 + r, NN - 1);
            float4 v;
            if (kg < INF)
                v = *(const float4*)(nf + (size_t)rr * INF + kg);
            else
                v = *(const float4*)(g_hneigh + (size_t)rr * HIDF + (kg - INF));
            uint4 o;
            o.x = f2tf(v.x); o.y = f2tf(v.y); o.z = f2tf(v.z); o.w = f2tf(v.w);
            *(uint4*)&As[r][kk] = o;
        }
        CP_COMMIT();
        cp_wait<0>();
        __syncthreads();
#pragma unroll
        for (int ks = 0; ks < TBK2; ks += 8) {
            uint32_t af[2][4], bf[4][2];
#pragma unroll
            for (int mt = 0; mt < 2; mt++) {
                int rb = wr * 32 + mt * 16;
                af[mt][0] = As[rb + g][ks + tig];
                af[mt][1] = As[rb + g + 8][ks + tig];
                af[mt][2] = As[rb + g][ks + tig + 4];
                af[mt][3] = As[rb + g + 8][ks + tig + 4];
            }
#pragma unroll
            for (int nt = 0; nt < 4; nt++) {
                int cb = wc * 32 + nt * 8;
                bf[nt][0] = Bs[ks + tig][cb + g];
                bf[nt][1] = Bs[ks + tig + 4][cb + g];
            }
#pragma unroll
            for (int mt = 0; mt < 2; mt++)
#pragma unroll
                for (int nt = 0; nt < 4; nt++)
                    mma_tf32(c[mt][nt], af[mt], bf[nt]);
        }
        __syncthreads();
    }
#pragma unroll
    for (int mt = 0; mt < 2; mt++) {
        int r1 = row0 + wr * 32 + mt * 16 + g;
        int r2 = r1 + 8;
#pragma unroll
        for (int nt = 0; nt < 4; nt++) {
            int lc = wc * 32 + nt * 8 + tig * 2;
            if (r1 < NN)
                *(float2*)(g_hn1 + (size_t)r1 * HIDF + lc) =
                    make_float2(silu_f(c[mt][nt][0] + s_b[lc]),
                                silu_f(c[mt][nt][1] + s_b[lc + 1]));
            if (r2 < NN)
                *(float2*)(g_hn1 + (size_t)r2 * HIDF + lc) =
                    make_float2(silu_f(c[mt][nt][2] + s_b[lc]),
                                silu_f(c[mt][nt][3] + s_b[lc + 1]));
        }
    }
}

// ---------------- node GEMM 2 + BN stats (fp32) ----------------
__global__ __launch_bounds__(256, 2)
void k_n2(const float* __restrict__ W, const float* __restrict__ b,
          float* __restrict__ out) {
    __shared__ float As[TBK][128 + 4];
    __shared__ float Bs[TBK][128 + 4];
    __shared__ float csum[128];
    __shared__ float csq[128];
    const int tid = threadIdx.x;
    const int row0 = blockIdx.x * 128;
    if (tid < 128) { csum[tid] = 0.0f; csq[tid] = 0.0f; }
    const int tx = tid & 15;
    const int ty = tid >> 4;
    u64 acc2[8][4];
#pragma unroll
    for (int i = 0; i < 8; i++)
#pragma unroll
        for (int j = 0; j < 4; j++) acc2[i][j] = 0ull;

    for (int kt = 0; kt < HIDF / TBK; kt++) {
#pragma unroll
        for (int i = 0; i < 2; i++) {
            int f = tid + i * 256;
            int r = f >> 2;
            int kk = (f & 3) << 2;
            int rr = min(row0 + r, NN - 1);
            float4 v = *(const float4*)(g_hn1 + (size_t)rr * HIDF + kt * TBK + kk);
            As[kk + 0][r] = v.x; As[kk + 1][r] = v.y;
            As[kk + 2][r] = v.z; As[kk + 3][r] = v.w;
        }
#pragma unroll
        for (int i = 0; i < 2; i++) {
            int f = tid + i * 256;
            int kk = f >> 5;
            int c = (f & 31) << 2;
            *(float4*)&Bs[kk][c] =
                *(const float4*)(W + (size_t)(kt * TBK + kk) * OUTF + c);
        }
        __syncthreads();
#pragma unroll
        for (int k = 0; k < TBK; k++)
            mt_step(acc2, &As[k][0], &Bs[k][0], ty * 8, tx * 8);
        __syncthreads();
    }
    float bb[8];
#pragma unroll
    for (int j = 0; j < 8; j++) bb[j] = b[tx * 8 + j];
    float cs[8], cq[8];
#pragma unroll
    for (int j = 0; j < 8; j++) { cs[j] = 0.0f; cq[j] = 0.0f; }
#pragma unroll
    for (int i = 0; i < 8; i++) {
        int row = row0 + ty * 8 + i;
        if (row < NN) {
            float a[8], h[8];
#pragma unroll
            for (int jp = 0; jp < 4; jp++) upk2(acc2[i][jp], a[2 * jp], a[2 * jp + 1]);
#pragma unroll
            for (int j = 0; j < 8; j++) {
                h[j] = a[j] + bb[j];
                cs[j] += h[j];
                cq[j] += h[j] * h[j];
            }
            *(float4*)(out + (size_t)row * OUTF + tx * 8) =
                make_float4(h[0], h[1], h[2], h[3]);
            *(float4*)(out + (size_t)row * OUTF + tx * 8 + 4) =
                make_float4(h[4], h[5], h[6], h[7]);
        }
    }
#pragma unroll
    for (int j = 0; j < 8; j++) {
        atomicAdd(&csum[tx * 8 + j], cs[j]);
        atomicAdd(&csq[tx * 8 + j], cq[j]);
    }
    __syncthreads();
    if (tid < 128) {
        atomicAdd(&g_colsum[tid], csum[tid]);
        atomicAdd(&g_colsq[tid], csq[tid]);
    }
}

// ---------------- x output ----------------
__global__ void k_xout(const float* __restrict__ coord, float* __restrict__ out) {
    int n = blockIdx.x * blockDim.x + threadIdx.x;
    if (n >= NN) return;
    float inv = 1.0f / fmaxf(g_deg[n], 1.0f);
    float* o = out + (size_t)NN * OUTF + n * 3;
    o[0] = coord[n * 3 + 0] + g_xsum[n * 3 + 0] * inv;
    o[1] = coord[n * 3 + 1] + g_xsum[n * 3 + 1] * inv;
    o[2] = coord[n * 3 + 2] + g_xsum[n * 3 + 2] * inv;
}

// ---------------- BatchNorm finalize ----------------
__global__ void k_bn(const float* __restrict__ gamma, const float* __restrict__ beta,
                     float* __restrict__ out) {
    int idx = blockIdx.x * blockDim.x + threadIdx.x;
    if (idx >= NN * OUTF) return;
    int c = idx & (OUTF - 1);
    const float invN = 1.0f / (float)NN;
    float mu = g_colsum[c] * invN;
    float var = g_colsq[c] * invN - mu * mu;
    float h = out[idx];
    out[idx] = (h - mu) * rsqrtf(var + 1e-5f) * gamma[c] + beta[c];
}

// ---------------- launch ----------------
extern "C" void kernel_launch(void* const* d_in, const int* in_sizes, int n_in,
                              void* d_out, int out_size) {
    const float* nf    = (const float*)d_in[0];
    const float* coord = (const float*)d_in[1];
    const int*   src   = (const int*)d_in[2];
    const int*   dst   = (const int*)d_in[3];
    const float* We1   = (const float*)d_in[4];
    const float* be1   = (const float*)d_in[5];
    const float* We2   = (const float*)d_in[6];
    const float* be2   = (const float*)d_in[7];
    const float* Wc1   = (const float*)d_in[8];
    const float* bc1   = (const float*)d_in[9];
    const float* Wc2   = (const float*)d_in[10];
    const float* Wn1   = (const float*)d_in[11];
    const float* bn1   = (const float*)d_in[12];
    const float* Wn2   = (const float*)d_in[13];
    const float* bn2   = (const float*)d_in[14];
    const float* gamma = (const float*)d_in[15];
    const float* beta  = (const float*)d_in[16];
    float* out = (float*)d_out;

    cudaFuncSetAttribute(k_e2c, cudaFuncAttributeMaxDynamicSharedMemorySize, E2C_SMEM_BYTES);

    void* p;
    cudaGetSymbolAddress(&p, g_hneigh);
    cudaMemsetAsync(p, 0, sizeof(float) * (size_t)NN * HIDF);
    cudaGetSymbolAddress(&p, g_xsum);
    cudaMemsetAsync(p, 0, sizeof(float) * NN * 3);
    cudaGetSymbolAddress(&p, g_deg);
    cudaMemsetAsync(p, 0, sizeof(float) * NN);
    cudaGetSymbolAddress(&p, g_colsum);
    cudaMemsetAsync(p, 0, sizeof(float) * OUTF);
    cudaGetSymbolAddress(&p, g_colsq);
    cudaMemsetAsync(p, 0, sizeof(float) * OUTF);

    k_cvtw<<<(KN1 * HIDF + 255) / 256, 256>>>(We1, Wn1);
    k_wth<<<(HIDF * HIDF + 255) / 256, 256>>>(We2, Wc1);
    k_geom<<<(NE + 255) / 256, 256>>>(coord, src, dst);

    dim3 gp((NN + 63) / 64, 2);
    k_pre_tf<<<gp, 512>>>(nf);

    k_e2c<<<NE / 128, 1024, E2C_SMEM_BYTES>>>(src, dst, We1 + (size_t)2 * INF * HIDF,
                                              be1, be2, bc1, Wc2);

    k_n1_tf<<<(NN + 63) / 64, 512>>>(nf, bn1);
    k_n2<<<(NN + 127) / 128, 256>>>(Wn2, bn2, out);

    k_xout<<<(NN + 255) / 256, 256>>>(coord, out);
    k_bn<<<(NN * OUTF + 255) / 256, 256>>>(gamma, beta, out);
}

// round 16
// speedup vs baseline: 1.2310x; 1.2310x over previous
#include <cuda_runtime.h>
#include <cuda_fp16.h>
#include <math.h>
#include <stdint.h>

#define NN 50000
#define NE 800000
#define INF 128
#define HIDF 256
#define OUTF 128
#define KN1 384
#define TBK 16
#define TBK2 32

// tf32 helper strides (pre/n1)
#define BS_STRIDE 264
#define AS_STRIDE 36

// fused f16 kernel SMEM layout (u32 units) -- 64-edge tile, K-chunk 64
#define MS_STR 132            // 128 u32 (256 halves) + 4 pad (132 % 32 == 4)
#define AS_STR 36             // 32 u32 (64 halves) + 4 pad
#define BS_STR 36
#define U_MS 0                // 64*132 = 8448 (phase-1 As aliases head: 64*36=2304)
#define U_BS 8448             // 2 bufs x 256 rows x 36 = 18432
#define U_F  27392
#define U_WR   (U_F)
#define U_B1   (U_F + 256)
#define U_B2   (U_F + 512)
#define U_BC1  (U_F + 768)
#define U_W2   (U_F + 1024)
#define U_RAD  (U_F + 1280)
#define U_RED  (U_F + 1344)
#define U_SRC  (U_F + 1408)
#define U_DST  (U_F + 1472)
#define E2C_SMEM_BYTES ((U_F + 1536) * 4)   // 115712

typedef unsigned long long u64;

__device__ __forceinline__ float silu_f(float x) {
    return x * (1.0f / (1.0f + __expf(-x)));
}

// ---- packed f32x2 helpers (fp32 k_n2) ----
__device__ __forceinline__ u64 pk2(float lo, float hi) {
    u64 r; asm("mov.b64 %0, {%1, %2};" : "=l"(r) : "f"(lo), "f"(hi)); return r;
}
__device__ __forceinline__ u64 pkb(float x) {
    u64 r; asm("mov.b64 %0, {%1, %1};" : "=l"(r) : "f"(x)); return r;
}
__device__ __forceinline__ void upk2(u64 v, float& lo, float& hi) {
    asm("mov.b64 {%0, %1}, %2;" : "=f"(lo), "=f"(hi) : "l"(v));
}
__device__ __forceinline__ void fma2(u64& acc, u64 a, u64 b) {
    asm("fma.rn.f32x2 %0, %1, %2, %0;" : "+l"(acc) : "l"(a), "l"(b));
}
__device__ __forceinline__ void mt_step(u64 (&acc2)[8][4], const float* __restrict__ Arow,
                                        const float* __restrict__ Brow, int ty8, int tx8) {
    float4 a0 = *(const float4*)(Arow + ty8);
    float4 a1 = *(const float4*)(Arow + ty8 + 4);
    float4 b0 = *(const float4*)(Brow + tx8);
    float4 b1 = *(const float4*)(Brow + tx8 + 4);
    float ar[8] = {a0.x, a0.y, a0.z, a0.w, a1.x, a1.y, a1.z, a1.w};
    u64 br2[4] = {pk2(b0.x, b0.y), pk2(b0.z, b0.w), pk2(b1.x, b1.y), pk2(b1.z, b1.w)};
#pragma unroll
    for (int i = 0; i < 8; i++) {
        u64 aa = pkb(ar[i]);
#pragma unroll
        for (int jp = 0; jp < 4; jp++) fma2(acc2[i][jp], aa, br2[jp]);
    }
}

// ---- tf32 mma (pre/n1) ----
__device__ __forceinline__ uint32_t f2tf(float x) {
    uint32_t r; asm("cvt.rna.tf32.f32 %0, %1;" : "=r"(r) : "f"(x)); return r;
}
__device__ __forceinline__ void mma_tf32(float (&c)[4], const uint32_t (&a)[4],
                                         const uint32_t (&b)[2]) {
    asm("mma.sync.aligned.m16n8k8.row.col.f32.tf32.tf32.f32 "
        "{%0,%1,%2,%3}, {%4,%5,%6,%7}, {%8,%9}, {%0,%1,%2,%3};"
        : "+f"(c[0]), "+f"(c[1]), "+f"(c[2]), "+f"(c[3])
        : "r"(a[0]), "r"(a[1]), "r"(a[2]), "r"(a[3]), "r"(b[0]), "r"(b[1]));
}

// ---- f16 mma m16n8k16 ----
__device__ __forceinline__ void mma_f16(float (&c)[4], const uint32_t (&a)[4],
                                        const uint32_t (&b)[2]) {
    asm("mma.sync.aligned.m16n8k16.row.col.f32.f16.f16.f32 "
        "{%0,%1,%2,%3}, {%4,%5,%6,%7}, {%8,%9}, {%0,%1,%2,%3};"
        : "+f"(c[0]), "+f"(c[1]), "+f"(c[2]), "+f"(c[3])
        : "r"(a[0]), "r"(a[1]), "r"(a[2]), "r"(a[3]), "r"(b[0]), "r"(b[1]));
}

__device__ __forceinline__ uint32_t h2u(float lo, float hi) {
    __half2 h = __floats2half2_rn(lo, hi);
    return *(uint32_t*)&h;
}

__device__ __forceinline__ void red_v2(float* p, float a, float b) {
    asm volatile("red.global.add.v2.f32 [%0], {%1, %2};"
                 :: "l"(p), "f"(a), "f"(b) : "memory");
}
__device__ __forceinline__ void cp16(uint32_t s_addr, const void* g) {
    asm volatile("cp.async.cg.shared.global [%0], [%1], 16;" :: "r"(s_addr), "l"(g));
}
#define CP_COMMIT() asm volatile("cp.async.commit_group;")
template <int N>
__device__ __forceinline__ void cp_wait() {
    asm volatile("cp.async.wait_group %0;" :: "n"(N));
}

// ---------------- scratch ----------------
__device__ float g_xdiff[NE * 4];
__device__ float g_pa[(size_t)NN * HIDF];
__device__ float g_pb[(size_t)NN * HIDF];
__device__ float g_hneigh[(size_t)NN * HIDF];
__device__ float g_xsum[NN * 3];
__device__ float g_deg[NN];
__device__ float g_hn1[(size_t)NN * HIDF];
__device__ float g_colsum[OUTF];
__device__ float g_colsq[OUTF];
__device__ uint32_t g_wt_e1[2 * INF * HIDF];     // tf32
__device__ uint32_t g_wt_n1[KN1 * HIDF];         // tf32
__device__ uint32_t g_wth_e2[HIDF * HIDF / 2];   // half, transposed [n][k]
__device__ uint32_t g_wth_c1[HIDF * HIDF / 2];   // half, transposed [n][k]

// ---------------- weight preps ----------------
__global__ void k_cvtw(const float* __restrict__ We1, const float* __restrict__ Wn1) {
    int i = blockIdx.x * blockDim.x + threadIdx.x;
    if (i < 2 * INF * HIDF) g_wt_e1[i] = f2tf(We1[i]);
    if (i < KN1 * HIDF) g_wt_n1[i] = f2tf(Wn1[i]);
}
__global__ void k_wth(const float* __restrict__ We2, const float* __restrict__ Wc1) {
    int i = blockIdx.x * blockDim.x + threadIdx.x;
    if (i >= HIDF * HIDF) return;
    int k = i >> 8, n = i & 255;
    ((__half*)g_wth_e2)[n * 256 + k] = __float2half(We2[i]);
    ((__half*)g_wth_c1)[n * 256 + k] = __float2half(Wc1[i]);
}

// ---------------- edge geometry ----------------
__global__ void k_geom(const float* __restrict__ coord,
                       const int* __restrict__ src,
                       const int* __restrict__ dst) {
    int e = blockIdx.x * blockDim.x + threadIdx.x;
    if (e >= NE) return;
    int s = src[e], d = dst[e];
    float ax = coord[s * 3 + 0], ay = coord[s * 3 + 1], az = coord[s * 3 + 2];
    float bx = coord[d * 3 + 0], by = coord[d * 3 + 1], bz = coord[d * 3 + 2];
    float dx = ax - bx, dy = ay - by, dz = az - bz;
    float r = dx * dx + dy * dy + dz * dz;
    float inv = 1.0f / (sqrtf(r) + 1e-30f);
    ((float4*)g_xdiff)[e] = make_float4(dx * inv, dy * inv, dz * inv, r);
    atomicAdd(&g_deg[d], 1.0f);
}

// ---------------- node pre-GEMM (tf32) ----------------
__global__ __launch_bounds__(512, 2)
void k_pre_tf(const float* __restrict__ nf) {
    __shared__ uint32_t As[64][AS_STRIDE];
    __shared__ uint32_t Bs[TBK2][BS_STRIDE];
    const int tid = threadIdx.x;
    const int row0 = blockIdx.x * 64;
    const int z = blockIdx.y;
    float* out = z ? g_pb : g_pa;
    const uint32_t bs_base = (uint32_t)__cvta_generic_to_shared(&Bs[0][0]);
    const int lane = tid & 31;
    const int g = lane >> 2;
    const int tig = lane & 3;
    const int wid = tid >> 5;
    const int wr = wid >> 3;
    const int wc = wid & 7;
    float c[2][4][4];
#pragma unroll
    for (int mt = 0; mt < 2; mt++)
#pragma unroll
        for (int nt = 0; nt < 4; nt++)
#pragma unroll
            for (int q = 0; q < 4; q++) c[mt][nt][q] = 0.0f;

    for (int kt = 0; kt < INF / TBK2; kt++) {
#pragma unroll
        for (int i = 0; i < 4; i++) {
            int f = tid + i * 512;
            int kk = f >> 6;
            int cc = (f & 63) << 2;
            cp16(bs_base + (uint32_t)(kk * BS_STRIDE + cc) * 4,
                 g_wt_e1 + (size_t)(z * INF + kt * TBK2 + kk) * HIDF + cc);
        }
        {
            int r = tid >> 3;
            int kk = (tid & 7) << 2;
            int rr = min(row0 + r, NN - 1);
            float4 v = *(const float4*)(nf + (size_t)rr * INF + kt * TBK2 + kk);
            uint4 o;
            o.x = f2tf(v.x); o.y = f2tf(v.y); o.z = f2tf(v.z); o.w = f2tf(v.w);
            *(uint4*)&As[r][kk] = o;
        }
        CP_COMMIT();
        cp_wait<0>();
        __syncthreads();
#pragma unroll
        for (int ks = 0; ks < TBK2; ks += 8) {
            uint32_t af[2][4], bf[4][2];
#pragma unroll
            for (int mt = 0; mt < 2; mt++) {
                int rb = wr * 32 + mt * 16;
                af[mt][0] = As[rb + g][ks + tig];
                af[mt][1] = As[rb + g + 8][ks + tig];
                af[mt][2] = As[rb + g][ks + tig + 4];
                af[mt][3] = As[rb + g + 8][ks + tig + 4];
            }
#pragma unroll
            for (int nt = 0; nt < 4; nt++) {
                int cb = wc * 32 + nt * 8;
                bf[nt][0] = Bs[ks + tig][cb + g];
                bf[nt][1] = Bs[ks + tig + 4][cb + g];
            }
#pragma unroll
            for (int mt = 0; mt < 2; mt++)
#pragma unroll
                for (int nt = 0; nt < 4; nt++)
                    mma_tf32(c[mt][nt], af[mt], bf[nt]);
        }
        __syncthreads();
    }
#pragma unroll
    for (int mt = 0; mt < 2; mt++) {
        int r1 = row0 + wr * 32 + mt * 16 + g;
        int r2 = r1 + 8;
#pragma unroll
        for (int nt = 0; nt < 4; nt++) {
            int lc = wc * 32 + nt * 8 + tig * 2;
            if (r1 < NN)
                *(float2*)(out + (size_t)r1 * HIDF + lc) =
                    make_float2(c[mt][nt][0], c[mt][nt][1]);
            if (r2 < NN)
                *(float2*)(out + (size_t)r2 * HIDF + lc) =
                    make_float2(c[mt][nt][2], c[mt][nt][3]);
        }
    }
}

// ---------------- FUSED edge kernel (f16 m16n8k16, 64-edge tile, K-chunk 64) ----------------
__global__ __launch_bounds__(512, 2)
void k_e2c(const int* __restrict__ src, const int* __restrict__ dst,
           const float* __restrict__ W1row, const float* __restrict__ b1,
           const float* __restrict__ b2, const float* __restrict__ bc1,
           const float* __restrict__ Wc2) {
    extern __shared__ uint32_t sm[];
    uint32_t* sm_ms = sm + U_MS;        // msg_h half tile, 64 x MS_STR
    uint32_t* sm_as = sm + U_MS;        // phase-1 gather chunk (aliases head)
    uint32_t* sm_bs = sm + U_BS;        // B half chunks, 2 x 256 x BS_STR
    float* s_wr  = (float*)(sm + U_WR);
    float* s_b1  = (float*)(sm + U_B1);
    float* s_b2  = (float*)(sm + U_B2);
    float* s_bc1 = (float*)(sm + U_BC1);
    float* s_w2  = (float*)(sm + U_W2);
    float* s_rad = (float*)(sm + U_RAD);
    float* s_red = (float*)(sm + U_RED);
    int*   s_src = (int*)(sm + U_SRC);
    int*   s_dst = (int*)(sm + U_DST);

    const int tid = threadIdx.x;
    const int row0 = blockIdx.x * 64;
    if (tid < 64) {
        int e = row0 + tid;
        s_src[tid] = src[e];
        s_dst[tid] = dst[e];
        s_rad[tid] = g_xdiff[e * 4 + 3];
        s_red[tid] = 0.0f;
    }
    if (tid < HIDF) {
        s_wr[tid] = W1row[tid];
        s_b1[tid] = b1[tid];
        s_b2[tid] = b2[tid];
        s_bc1[tid] = bc1[tid];
        s_w2[tid] = Wc2[tid];
    }
    __syncthreads();
    const uint32_t bs_base = (uint32_t)__cvta_generic_to_shared(sm_bs);
    const int lane = tid & 31;
    const int g = lane >> 2;
    const int tig = lane & 3;
    const int wid = tid >> 5;
    const int wr = wid >> 3;   // 0..1 -> 32 rows each
    const int wc = wid & 7;    // 0..7 -> 32 cols each
    float c[2][4][4];
#pragma unroll
    for (int mt = 0; mt < 2; mt++)
#pragma unroll
        for (int nt = 0; nt < 4; nt++)
#pragma unroll
            for (int q = 0; q < 4; q++) c[mt][nt][q] = 0.0f;

    // B chunk: 256 n-rows x 32 u32 (64 halves) = 2048 cp16, 4/thread
#define ISSUE_B(WTH, KB, BUF)                                                    \
    {                                                                            \
        _Pragma("unroll")                                                        \
        for (int i = 0; i < 4; i++) {                                            \
            int f = tid + i * 512;                                               \
            int n = f >> 3;                                                      \
            int j = (f & 7) << 2;                                                \
            cp16(bs_base + (uint32_t)(((BUF) * 256 + n) * BS_STR + j) * 4,       \
                 (WTH) + (size_t)n * 128 + (KB) * 32 + j);                       \
        }                                                                        \
    }

    // ================= phase 1: msg_h = silu(A @ W_e2 + b2) =================
    ISSUE_B(g_wth_e2, 0, 0);
    CP_COMMIT();
    for (int kb = 0; kb < 4; kb++) {     // K chunks of 64
        const int buf = kb & 1;
        // A staging: 64 rows x 64 halves; thread -> 8 halves (uint4)
        {
            int r = tid >> 3;
            int k8 = (tid & 7) << 3;
            int kg = kb * 64 + k8;
            const float4* pa = (const float4*)(g_pa + (size_t)s_src[r] * HIDF + kg);
            const float4* pb = (const float4*)(g_pb + (size_t)s_dst[r] * HIDF + kg);
            float4 a0 = pa[0], a1 = pa[1], q0 = pb[0], q1 = pb[1];
            float rad = s_rad[r];
            float v0 = silu_f(a0.x + q0.x + rad * s_wr[kg + 0] + s_b1[kg + 0]);
            float v1 = silu_f(a0.y + q0.y + rad * s_wr[kg + 1] + s_b1[kg + 1]);
            float v2 = silu_f(a0.z + q0.z + rad * s_wr[kg + 2] + s_b1[kg + 2]);
            float v3 = silu_f(a0.w + q0.w + rad * s_wr[kg + 3] + s_b1[kg + 3]);
            float v4 = silu_f(a1.x + q1.x + rad * s_wr[kg + 4] + s_b1[kg + 4]);
            float v5 = silu_f(a1.y + q1.y + rad * s_wr[kg + 5] + s_b1[kg + 5]);
            float v6 = silu_f(a1.z + q1.z + rad * s_wr[kg + 6] + s_b1[kg + 6]);
            float v7 = silu_f(a1.w + q1.w + rad * s_wr[kg + 7] + s_b1[kg + 7]);
            uint4 o;
            o.x = h2u(v0, v1); o.y = h2u(v2, v3);
            o.z = h2u(v4, v5); o.w = h2u(v6, v7);
            *(uint4*)&sm_as[r * AS_STR + (k8 >> 1)] = o;
        }
        if (kb + 1 < 4) {
            ISSUE_B(g_wth_e2, kb + 1, buf ^ 1);
            CP_COMMIT();
            cp_wait<1>();
        } else {
            cp_wait<0>();
        }
        __syncthreads();
#pragma unroll
        for (int ks = 0; ks < 4; ks++) {   // four k16 steps
            const int kb2 = ks * 8;
            uint32_t af[2][4], bf[4][2];
#pragma unroll
            for (int mt = 0; mt < 2; mt++) {
                int rb = wr * 32 + mt * 16;
                af[mt][0] = sm_as[(rb + g) * AS_STR + kb2 + tig];
                af[mt][1] = sm_as[(rb + g + 8) * AS_STR + kb2 + tig];
                af[mt][2] = sm_as[(rb + g) * AS_STR + kb2 + tig + 4];
                af[mt][3] = sm_as[(rb + g + 8) * AS_STR + kb2 + tig + 4];
            }
#pragma unroll
            for (int nt = 0; nt < 4; nt++) {
                int cb = wc * 32 + nt * 8;
                bf[nt][0] = sm_bs[(buf * 256 + cb + g) * BS_STR + kb2 + tig];
                bf[nt][1] = sm_bs[(buf * 256 + cb + g) * BS_STR + kb2 + tig + 4];
            }
#pragma unroll
            for (int mt = 0; mt < 2; mt++)
#pragma unroll
                for (int nt = 0; nt < 4; nt++)
                    mma_f16(c[mt][nt], af[mt], bf[nt]);
        }
        __syncthreads();
    }
    // ---- epilogue 1: bias+silu, stash msg_h as half, h_neigh reduce ----
#pragma unroll
    for (int mt = 0; mt < 2; mt++) {
        int r1 = wr * 32 + mt * 16 + g;
        int r2 = r1 + 8;
        int d1 = s_dst[r1], d2 = s_dst[r2];
#pragma unroll
        for (int nt = 0; nt < 4; nt++) {
            int lc = wc * 32 + nt * 8 + tig * 2;
            float v0 = silu_f(c[mt][nt][0] + s_b2[lc]);
            float v1 = silu_f(c[mt][nt][1] + s_b2[lc + 1]);
            float v2 = silu_f(c[mt][nt][2] + s_b2[lc]);
            float v3 = silu_f(c[mt][nt][3] + s_b2[lc + 1]);
            sm_ms[r1 * MS_STR + (lc >> 1)] = h2u(v0, v1);
            sm_ms[r2 * MS_STR + (lc >> 1)] = h2u(v2, v3);
            red_v2(g_hneigh + (size_t)d1 * HIDF + lc, v0, v1);
            red_v2(g_hneigh + (size_t)d2 * HIDF + lc, v2, v3);
        }
    }
    __syncthreads();

    // ================= phase 2: t = msg_h @ W_c1 (A resident as half) =================
#pragma unroll
    for (int mt = 0; mt < 2; mt++)
#pragma unroll
        for (int nt = 0; nt < 4; nt++)
#pragma unroll
            for (int q = 0; q < 4; q++) c[mt][nt][q] = 0.0f;

    ISSUE_B(g_wth_c1, 0, 0);
    CP_COMMIT();
    for (int kb = 0; kb < 4; kb++) {
        const int buf = kb & 1;
        if (kb + 1 < 4) {
            ISSUE_B(g_wth_c1, kb + 1, buf ^ 1);
            CP_COMMIT();
            cp_wait<1>();
        } else {
            cp_wait<0>();
        }
        __syncthreads();
#pragma unroll
        for (int ks = 0; ks < 4; ks++) {
            const int ku = kb * 32 + ks * 8;   // u32 col in ms
            const int kb2 = ks * 8;
            uint32_t af[2][4], bf[4][2];
#pragma unroll
            for (int mt = 0; mt < 2; mt++) {
                int rb = wr * 32 + mt * 16;
                af[mt][0] = sm_ms[(rb + g) * MS_STR + ku + tig];
                af[mt][1] = sm_ms[(rb + g + 8) * MS_STR + ku + tig];
                af[mt][2] = sm_ms[(rb + g) * MS_STR + ku + tig + 4];
                af[mt][3] = sm_ms[(rb + g + 8) * MS_STR + ku + tig + 4];
            }
#pragma unroll
            for (int nt = 0; nt < 4; nt++) {
                int cb = wc * 32 + nt * 8;
                bf[nt][0] = sm_bs[(buf * 256 + cb + g) * BS_STR + kb2 + tig];
                bf[nt][1] = sm_bs[(buf * 256 + cb + g) * BS_STR + kb2 + tig + 4];
            }
#pragma unroll
            for (int mt = 0; mt < 2; mt++)
#pragma unroll
                for (int nt = 0; nt < 4; nt++)
                    mma_f16(c[mt][nt], af[mt], bf[nt]);
        }
        __syncthreads();
    }
    // ---- epilogue 2: s = sum silu(t+bc1)*w2 ; scatter x_sum ----
#pragma unroll
    for (int mt = 0; mt < 2; mt++) {
        float s1 = 0.0f, s2 = 0.0f;
#pragma unroll
        for (int nt = 0; nt < 4; nt++) {
            int lc = wc * 32 + nt * 8 + tig * 2;
            s1 += silu_f(c[mt][nt][0] + s_bc1[lc]) * s_w2[lc]
                + silu_f(c[mt][nt][1] + s_bc1[lc + 1]) * s_w2[lc + 1];
            s2 += silu_f(c[mt][nt][2] + s_bc1[lc]) * s_w2[lc]
                + silu_f(c[mt][nt][3] + s_bc1[lc + 1]) * s_w2[lc + 1];
        }
        s1 += __shfl_xor_sync(0xffffffffu, s1, 1);
        s1 += __shfl_xor_sync(0xffffffffu, s1, 2);
        s2 += __shfl_xor_sync(0xffffffffu, s2, 1);
        s2 += __shfl_xor_sync(0xffffffffu, s2, 2);
        if (tig == 0) {
            atomicAdd(&s_red[wr * 32 + mt * 16 + g], s1);
            atomicAdd(&s_red[wr * 32 + mt * 16 + g + 8], s2);
        }
    }
    __syncthreads();
    if (tid < 64) {
        int e = row0 + tid;
        float s = s_red[tid];
        float4 xd = *(const float4*)(g_xdiff + (size_t)e * 4);
        int d = s_dst[tid];
        atomicAdd(&g_xsum[d * 3 + 0], s * xd.x);
        atomicAdd(&g_xsum[d * 3 + 1], s * xd.y);
        atomicAdd(&g_xsum[d * 3 + 2], s * xd.z);
    }
#undef ISSUE_B
}

// ---------------- node GEMM 1 (tf32) ----------------
__global__ __launch_bounds__(512, 2)
void k_n1_tf(const float* __restrict__ nf, const float* __restrict__ b) {
    __shared__ uint32_t As[64][AS_STRIDE];
    __shared__ uint32_t Bs[TBK2][BS_STRIDE];
    __shared__ float s_b[HIDF];
    const int tid = threadIdx.x;
    const int row0 = blockIdx.x * 64;
    if (tid < HIDF) s_b[tid] = b[tid];
    const uint32_t bs_base = (uint32_t)__cvta_generic_to_shared(&Bs[0][0]);
    const int lane = tid & 31;
    const int g = lane >> 2;
    const int tig = lane & 3;
    const int wid = tid >> 5;
    const int wr = wid >> 3;
    const int wc = wid & 7;
    float c[2][4][4];
#pragma unroll
    for (int mt = 0; mt < 2; mt++)
#pragma unroll
        for (int nt = 0; nt < 4; nt++)
#pragma unroll
            for (int q = 0; q < 4; q++) c[mt][nt][q] = 0.0f;
    __syncthreads();

    for (int kt = 0; kt < KN1 / TBK2; kt++) {
#pragma unroll
        for (int i = 0; i < 4; i++) {
            int f = tid + i * 512;
            int kk = f >> 6;
            int cc = (f & 63) << 2;
            cp16(bs_base + (uint32_t)(kk * BS_STRIDE + cc) * 4,
                 g_wt_n1 + (size_t)(kt * TBK2 + kk) * HIDF + cc);
        }
        {
            int r = tid >> 3;
            int kk = (tid & 7) << 2;
            int kg = kt * TBK2 + kk;
            int rr = min(row0 + r, NN - 1);
            float4 v;
            if (kg < INF)
                v = *(const float4*)(nf + (size_t)rr * INF + kg);
            else
                v = *(const float4*)(g_hneigh + (size_t)rr * HIDF + (kg - INF));
            uint4 o;
            o.x = f2tf(v.x); o.y = f2tf(v.y); o.z = f2tf(v.z); o.w = f2tf(v.w);
            *(uint4*)&As[r][kk] = o;
        }
        CP_COMMIT();
        cp_wait<0>();
        __syncthreads();
#pragma unroll
        for (int ks = 0; ks < TBK2; ks += 8) {
            uint32_t af[2][4], bf[4][2];
#pragma unroll
            for (int mt = 0; mt < 2; mt++) {
                int rb = wr * 32 + mt * 16;
                af[mt][0] = As[rb + g][ks + tig];
                af[mt][1] = As[rb + g + 8][ks + tig];
                af[mt][2] = As[rb + g][ks + tig + 4];
                af[mt][3] = As[rb + g + 8][ks + tig + 4];
            }
#pragma unroll
            for (int nt = 0; nt < 4; nt++) {
                int cb = wc * 32 + nt * 8;
                bf[nt][0] = Bs[ks + tig][cb + g];
                bf[nt][1] = Bs[ks + tig + 4][cb + g];
            }
#pragma unroll
            for (int mt = 0; mt < 2; mt++)
#pragma unroll
                for (int nt = 0; nt < 4; nt++)
                    mma_tf32(c[mt][nt], af[mt], bf[nt]);
        }
        __syncthreads();
    }
#pragma unroll
    for (int mt = 0; mt < 2; mt++) {
        int r1 = row0 + wr * 32 + mt * 16 + g;
        int r2 = r1 + 8;
#pragma unroll
        for (int nt = 0; nt < 4; nt++) {
            int lc = wc * 32 + nt * 8 + tig * 2;
            if (r1 < NN)
                *(float2*)(g_hn1 + (size_t)r1 * HIDF + lc) =
                    make_float2(silu_f(c[mt][nt][0] + s_b[lc]),
                                silu_f(c[mt][nt][1] + s_b[lc + 1]));
            if (r2 < NN)
                *(float2*)(g_hn1 + (size_t)r2 * HIDF + lc) =
                    make_float2(silu_f(c[mt][nt][2] + s_b[lc]),
                                silu_f(c[mt][nt][3] + s_b[lc + 1]));
        }
    }
}

// ---------------- node GEMM 2 + BN stats (fp32) ----------------
__global__ __launch_bounds__(256, 2)
void k_n2(const float* __restrict__ W, const float* __restrict__ b,
          float* __restrict__ out) {
    __shared__ float As[TBK][128 + 4];
    __shared__ float Bs[TBK][128 + 4];
    __shared__ float csum[128];
    __shared__ float csq[128];
    const int tid = threadIdx.x;
    const int row0 = blockIdx.x * 128;
    if (tid < 128) { csum[tid] = 0.0f; csq[tid] = 0.0f; }
    const int tx = tid & 15;
    const int ty = tid >> 4;
    u64 acc2[8][4];
#pragma unroll
    for (int i = 0; i < 8; i++)
#pragma unroll
        for (int j = 0; j < 4; j++) acc2[i][j] = 0ull;

    for (int kt = 0; kt < HIDF / TBK; kt++) {
#pragma unroll
        for (int i = 0; i < 2; i++) {
            int f = tid + i * 256;
            int r = f >> 2;
            int kk = (f & 3) << 2;
            int rr = min(row0 + r, NN - 1);
            float4 v = *(const float4*)(g_hn1 + (size_t)rr * HIDF + kt * TBK + kk);
            As[kk + 0][r] = v.x; As[kk + 1][r] = v.y;
            As[kk + 2][r] = v.z; As[kk + 3][r] = v.w;
        }
#pragma unroll
        for (int i = 0; i < 2; i++) {
            int f = tid + i * 256;
            int kk = f >> 5;
            int c = (f & 31) << 2;
            *(float4*)&Bs[kk][c] =
                *(const float4*)(W + (size_t)(kt * TBK + kk) * OUTF + c);
        }
        __syncthreads();
#pragma unroll
        for (int k = 0; k < TBK; k++)
            mt_step(acc2, &As[k][0], &Bs[k][0], ty * 8, tx * 8);
        __syncthreads();
    }
    float bb[8];
#pragma unroll
    for (int j = 0; j < 8; j++) bb[j] = b[tx * 8 + j];
    float cs[8], cq[8];
#pragma unroll
    for (int j = 0; j < 8; j++) { cs[j] = 0.0f; cq[j] = 0.0f; }
#pragma unroll
    for (int i = 0; i < 8; i++) {
        int row = row0 + ty * 8 + i;
        if (row < NN) {
            float a[8], h[8];
#pragma unroll
            for (int jp = 0; jp < 4; jp++) upk2(acc2[i][jp], a[2 * jp], a[2 * jp + 1]);
#pragma unroll
            for (int j = 0; j < 8; j++) {
                h[j] = a[j] + bb[j];
                cs[j] += h[j];
                cq[j] += h[j] * h[j];
            }
            *(float4*)(out + (size_t)row * OUTF + tx * 8) =
                make_float4(h[0], h[1], h[2], h[3]);
            *(float4*)(out + (size_t)row * OUTF + tx * 8 + 4) =
                make_float4(h[4], h[5], h[6], h[7]);
        }
    }
#pragma unroll
    for (int j = 0; j < 8; j++) {
        atomicAdd(&csum[tx * 8 + j], cs[j]);
        atomicAdd(&csq[tx * 8 + j], cq[j]);
    }
    __syncthreads();
    if (tid < 128) {
        atomicAdd(&g_colsum[tid], csum[tid]);
        atomicAdd(&g_colsq[tid], csq[tid]);
    }
}

// ---------------- x output ----------------
__global__ void k_xout(const float* __restrict__ coord, float* __restrict__ out) {
    int n = blockIdx.x * blockDim.x + threadIdx.x;
    if (n >= NN) return;
    float inv = 1.0f / fmaxf(g_deg[n], 1.0f);
    float* o = out + (size_t)NN * OUTF + n * 3;
    o[0] = coord[n * 3 + 0] + g_xsum[n * 3 + 0] * inv;
    o[1] = coord[n * 3 + 1] + g_xsum[n * 3 + 1] * inv;
    o[2] = coord[n * 3 + 2] + g_xsum[n * 3 + 2] * inv;
}

// ---------------- BatchNorm finalize ----------------
__global__ void k_bn(const float* __restrict__ gamma, const float* __restrict__ beta,
                     float* __restrict__ out) {
    int idx = blockIdx.x * blockDim.x + threadIdx.x;
    if (idx >= NN * OUTF) return;
    int c = idx & (OUTF - 1);
    const float invN = 1.0f / (float)NN;
    float mu = g_colsum[c] * invN;
    float var = g_colsq[c] * invN - mu * mu;
    float h = out[idx];
    out[idx] = (h - mu) * rsqrtf(var + 1e-5f) * gamma[c] + beta[c];
}

// ---------------- launch ----------------
extern "C" void kernel_launch(void* const* d_in, const int* in_sizes, int n_in,
                              void* d_out, int out_size) {
    const float* nf    = (const float*)d_in[0];
    const float* coord = (const float*)d_in[1];
    const int*   src   = (const int*)d_in[2];
    const int*   dst   = (const int*)d_in[3];
    const float* We1   = (const float*)d_in[4];
    const float* be1   = (const float*)d_in[5];
    const float* We2   = (const float*)d_in[6];
    const float* be2   = (const float*)d_in[7];
    const float* Wc1   = (const float*)d_in[8];
    const float* bc1   = (const float*)d_in[9];
    const float* Wc2   = (const float*)d_in[10];
    const float* Wn1   = (const float*)d_in[11];
    const float* bn1   = (const float*)d_in[12];
    const float* Wn2   = (const float*)d_in[13];
    const float* bn2   = (const float*)d_in[14];
    const float* gamma = (const float*)d_in[15];
    const float* beta  = (const float*)d_in[16];
    float* out = (float*)d_out;

    cudaFuncSetAttribute(k_e2c, cudaFuncAttributeMaxDynamicSharedMemorySize, E2C_SMEM_BYTES);

    void* p;
    cudaGetSymbolAddress(&p, g_hneigh);
    cudaMemsetAsync(p, 0, sizeof(float) * (size_t)NN * HIDF);
    cudaGetSymbolAddress(&p, g_xsum);
    cudaMemsetAsync(p, 0, sizeof(float) * NN * 3);
    cudaGetSymbolAddress(&p, g_deg);
    cudaMemsetAsync(p, 0, sizeof(float) * NN);
    cudaGetSymbolAddress(&p, g_colsum);
    cudaMemsetAsync(p, 0, sizeof(float) * OUTF);
    cudaGetSymbolAddress(&p, g_colsq);
    cudaMemsetAsync(p, 0, sizeof(float) * OUTF);

    k_cvtw<<<(KN1 * HIDF + 255) / 256, 256>>>(We1, Wn1);
    k_wth<<<(HIDF * HIDF + 255) / 256, 256>>>(We2, Wc1);
    k_geom<<<(NE + 255) / 256, 256>>>(coord, src, dst);

    dim3 gp((NN + 63) / 64, 2);
    k_pre_tf<<<gp, 512>>>(nf);

    k_e2c<<<NE / 64, 512, E2C_SMEM_BYTES>>>(src, dst, We1 + (size_t)2 * INF * HIDF,
                                            be1, be2, bc1, Wc2);

    k_n1_tf<<<(NN + 63) / 64, 512>>>(nf, bn1);
    k_n2<<<(NN + 127) / 128, 256>>>(Wn2, bn2, out);

    k_xout<<<(NN + 255) / 256, 256>>>(coord, out);
    k_bn<<<(NN * OUTF + 255) / 256, 256>>>(gamma, beta, out);
}

// round 17
// speedup vs baseline: 1.3550x; 1.1007x over previous
#include <cuda_runtime.h>
#include <cuda_fp16.h>
#include <math.h>
#include <stdint.h>

#define NN 50000
#define NE 800000
#define INF 128
#define HIDF 256
#define OUTF 128
#define KN1 384
#define TBK 16

// fused f16 kernel SMEM layout (u32 units) -- 64-edge tile, K-chunk 64
#define MS_STR 132
#define AS_STR 36
#define BS_STR 36
#define U_MS 0
#define U_BS 8448
#define U_F  27392
#define U_WR   (U_F)
#define U_B1   (U_F + 256)
#define U_B2   (U_F + 512)
#define U_BC1  (U_F + 768)
#define U_W2   (U_F + 1024)
#define U_RAD  (U_F + 1280)
#define U_RED  (U_F + 1344)
#define U_SRC  (U_F + 1408)
#define U_DST  (U_F + 1472)
#define E2C_SMEM_BYTES ((U_F + 1536) * 4)   // 115712

// k_pre_f16 SMEM (u32): As 64x68, Bs 256x68
#define P_STR 68
#define PRE_U_AS 0
#define PRE_U_BS 4352
#define PRE_SMEM_BYTES ((4352 + 17408) * 4)   // 87040

// k_n1_f16 SMEM (u32): As 64x36, Bs 2x256x36, s_b 256
#define N1_U_AS 0
#define N1_U_BS 2304
#define N1_U_B  20736
#define N1_SMEM_BYTES ((20736 + 256) * 4)     // 83968

typedef unsigned long long u64;

__device__ __forceinline__ float silu_f(float x) {
    return x * (1.0f / (1.0f + __expf(-x)));
}

// ---- packed f32x2 helpers (fp32 k_n2) ----
__device__ __forceinline__ u64 pk2(float lo, float hi) {
    u64 r; asm("mov.b64 %0, {%1, %2};" : "=l"(r) : "f"(lo), "f"(hi)); return r;
}
__device__ __forceinline__ u64 pkb(float x) {
    u64 r; asm("mov.b64 %0, {%1, %1};" : "=l"(r) : "f"(x)); return r;
}
__device__ __forceinline__ void upk2(u64 v, float& lo, float& hi) {
    asm("mov.b64 {%0, %1}, %2;" : "=f"(lo), "=f"(hi) : "l"(v));
}
__device__ __forceinline__ void fma2(u64& acc, u64 a, u64 b) {
    asm("fma.rn.f32x2 %0, %1, %2, %0;" : "+l"(acc) : "l"(a), "l"(b));
}
__device__ __forceinline__ void mt_step(u64 (&acc2)[8][4], const float* __restrict__ Arow,
                                        const float* __restrict__ Brow, int ty8, int tx8) {
    float4 a0 = *(const float4*)(Arow + ty8);
    float4 a1 = *(const float4*)(Arow + ty8 + 4);
    float4 b0 = *(const float4*)(Brow + tx8);
    float4 b1 = *(const float4*)(Brow + tx8 + 4);
    float ar[8] = {a0.x, a0.y, a0.z, a0.w, a1.x, a1.y, a1.z, a1.w};
    u64 br2[4] = {pk2(b0.x, b0.y), pk2(b0.z, b0.w), pk2(b1.x, b1.y), pk2(b1.z, b1.w)};
#pragma unroll
    for (int i = 0; i < 8; i++) {
        u64 aa = pkb(ar[i]);
#pragma unroll
        for (int jp = 0; jp < 4; jp++) fma2(acc2[i][jp], aa, br2[jp]);
    }
}

// ---- f16 mma m16n8k16 ----
__device__ __forceinline__ void mma_f16(float (&c)[4], const uint32_t (&a)[4],
                                        const uint32_t (&b)[2]) {
    asm("mma.sync.aligned.m16n8k16.row.col.f32.f16.f16.f32 "
        "{%0,%1,%2,%3}, {%4,%5,%6,%7}, {%8,%9}, {%0,%1,%2,%3};"
        : "+f"(c[0]), "+f"(c[1]), "+f"(c[2]), "+f"(c[3])
        : "r"(a[0]), "r"(a[1]), "r"(a[2]), "r"(a[3]), "r"(b[0]), "r"(b[1]));
}

__device__ __forceinline__ uint32_t h2u(float lo, float hi) {
    __half2 h = __floats2half2_rn(lo, hi);
    return *(uint32_t*)&h;
}
__device__ __forceinline__ float2 u2f2(uint32_t u) {
    __half2 h = *(__half2*)&u;
    return __half22float2(h);
}

__device__ __forceinline__ void red_v2(float* p, float a, float b) {
    asm volatile("red.global.add.v2.f32 [%0], {%1, %2};"
                 :: "l"(p), "f"(a), "f"(b) : "memory");
}
__device__ __forceinline__ void cp16(uint32_t s_addr, const void* g) {
    asm volatile("cp.async.cg.shared.global [%0], [%1], 16;" :: "r"(s_addr), "l"(g));
}
#define CP_COMMIT() asm volatile("cp.async.commit_group;")
template <int N>
__device__ __forceinline__ void cp_wait() {
    asm volatile("cp.async.wait_group %0;" :: "n"(N));
}

// ---------------- scratch ----------------
__device__ float g_xdiff[NE * 4];
__device__ uint32_t g_pah[(size_t)NN * 128];     // P_a as half2
__device__ uint32_t g_pbh[(size_t)NN * 128];     // P_b as half2
__device__ float g_hneigh[(size_t)NN * HIDF];
__device__ float g_xsum[NN * 3];
__device__ float g_deg[NN];
__device__ float g_hn1[(size_t)NN * HIDF];
__device__ float g_colsum[OUTF];
__device__ float g_colsq[OUTF];
__device__ uint32_t g_wth_e2[HIDF * HIDF / 2];   // half [n][k=256]
__device__ uint32_t g_wth_c1[HIDF * HIDF / 2];   // half [n][k=256]
__device__ uint32_t g_wth_e1[2 * 256 * 64];      // half [z][n=256][k=128]
__device__ uint32_t g_wth_n1[256 * 192];         // half [n=256][k=384]

// ---------------- weight prep (all half images) ----------------
__global__ void k_wprep(const float* __restrict__ We1, const float* __restrict__ We2,
                        const float* __restrict__ Wc1, const float* __restrict__ Wn1) {
    int i = blockIdx.x * blockDim.x + threadIdx.x;
    if (i < HIDF * HIDF) {
        int k = i >> 8, n = i & 255;
        ((__half*)g_wth_e2)[n * 256 + k] = __float2half(We2[i]);
        ((__half*)g_wth_c1)[n * 256 + k] = __float2half(Wc1[i]);
        // W_e1 rows 0..255: z = k>>7, kk = k&127
        ((__half*)g_wth_e1)[(size_t)(k >> 7) * 32768 + n * 128 + (k & 127)] =
            __float2half(We1[i]);
    }
    if (i < KN1 * HIDF) {
        int k = i >> 8, n = i & 255;
        ((__half*)g_wth_n1)[n * 384 + k] = __float2half(Wn1[i]);
    }
}

// ---------------- edge geometry ----------------
__global__ void k_geom(const float* __restrict__ coord,
                       const int* __restrict__ src,
                       const int* __restrict__ dst) {
    int e = blockIdx.x * blockDim.x + threadIdx.x;
    if (e >= NE) return;
    int s = src[e], d = dst[e];
    float ax = coord[s * 3 + 0], ay = coord[s * 3 + 1], az = coord[s * 3 + 2];
    float bx = coord[d * 3 + 0], by = coord[d * 3 + 1], bz = coord[d * 3 + 2];
    float dx = ax - bx, dy = ay - by, dz = az - bz;
    float r = dx * dx + dy * dy + dz * dz;
    float inv = 1.0f / (sqrtf(r) + 1e-30f);
    ((float4*)g_xdiff)[e] = make_float4(dx * inv, dy * inv, dz * inv, r);
    atomicAdd(&g_deg[d], 1.0f);
}

// ---------------- node pre-GEMM (f16): P_{a,b} = nf @ W_{a,b}, output half ----------------
__global__ __launch_bounds__(512, 2)
void k_pre_f16(const float* __restrict__ nf) {
    extern __shared__ uint32_t sm[];
    uint32_t* As = sm + PRE_U_AS;    // 64 x P_STR
    uint32_t* Bs = sm + PRE_U_BS;    // 256 x P_STR
    const int tid = threadIdx.x;
    const int row0 = blockIdx.x * 64;
    const int z = blockIdx.y;
    uint32_t* out = z ? g_pbh : g_pah;
    const uint32_t bs_base = (uint32_t)__cvta_generic_to_shared(Bs);
    const int lane = tid & 31;
    const int g = lane >> 2;
    const int tig = lane & 3;
    const int wid = tid >> 5;
    const int wr = wid >> 3;
    const int wc = wid & 7;
    float c[2][4][4];
#pragma unroll
    for (int mt = 0; mt < 2; mt++)
#pragma unroll
        for (int nt = 0; nt < 4; nt++)
#pragma unroll
            for (int q = 0; q < 4; q++) c[mt][nt][q] = 0.0f;

    // B: 256 x 64 u32 = 4096 cp16, 8/thread
#pragma unroll
    for (int i = 0; i < 8; i++) {
        int f = tid + i * 512;
        int n = f >> 3;
        int j = (f & 7) << 3;   // 0..56 step 8... need 64 u32 per row: f&7 gives 8 slots of 8? 8*8=64 ✓ but cp16 is 4 u32
        // fix: 64 u32 / 4 = 16 cp16 per row; 256*16 = 4096; slot = f&15? recompute below
        (void)n; (void)j;
    }
    // corrected B load: 4096 cp16 total, 8 per thread
#pragma unroll
    for (int i = 0; i < 8; i++) {
        int f = tid + i * 512;      // 0..4095
        int n = f >> 4;             // 0..255
        int j = (f & 15) << 2;      // 0..60 step 4
        cp16(bs_base + (uint32_t)(n * P_STR + j) * 4,
             g_wth_e1 + (size_t)z * 32768 / 2 * 0 + (size_t)z * 16384 + n * 64 + j);
    }
    // A: 64 rows x 64 u32, thread -> 8 u32 (16 halves from 16 nf floats)
    {
        int r = tid >> 3;
        int j8 = (tid & 7) << 3;    // u32 offset 0..56
        int kg = j8 << 1;           // half/float index
        int rr = min(row0 + r, NN - 1);
        const float4* p = (const float4*)(nf + (size_t)rr * INF + kg);
        float4 f0 = p[0], f1 = p[1], f2 = p[2], f3 = p[3];
        uint4 o0, o1;
        o0.x = h2u(f0.x, f0.y); o0.y = h2u(f0.z, f0.w);
        o0.z = h2u(f1.x, f1.y); o0.w = h2u(f1.z, f1.w);
        o1.x = h2u(f2.x, f2.y); o1.y = h2u(f2.z, f2.w);
        o1.z = h2u(f3.x, f3.y); o1.w = h2u(f3.z, f3.w);
        *(uint4*)&As[r * P_STR + j8] = o0;
        *(uint4*)&As[r * P_STR + j8 + 4] = o1;
    }
    CP_COMMIT();
    cp_wait<0>();
    __syncthreads();
#pragma unroll
    for (int ks = 0; ks < 8; ks++) {      // 8 k16 steps = K128
        const int kb2 = ks * 8;
        uint32_t af[2][4], bf[4][2];
#pragma unroll
        for (int mt = 0; mt < 2; mt++) {
            int rb = wr * 32 + mt * 16;
            af[mt][0] = As[(rb + g) * P_STR + kb2 + tig];
            af[mt][1] = As[(rb + g + 8) * P_STR + kb2 + tig];
            af[mt][2] = As[(rb + g) * P_STR + kb2 + tig + 4];
            af[mt][3] = As[(rb + g + 8) * P_STR + kb2 + tig + 4];
        }
#pragma unroll
        for (int nt = 0; nt < 4; nt++) {
            int cb = wc * 32 + nt * 8;
            bf[nt][0] = Bs[(cb + g) * P_STR + kb2 + tig];
            bf[nt][1] = Bs[(cb + g) * P_STR + kb2 + tig + 4];
        }
#pragma unroll
        for (int mt = 0; mt < 2; mt++)
#pragma unroll
            for (int nt = 0; nt < 4; nt++)
                mma_f16(c[mt][nt], af[mt], bf[nt]);
    }
#pragma unroll
    for (int mt = 0; mt < 2; mt++) {
        int r1 = row0 + wr * 32 + mt * 16 + g;
        int r2 = r1 + 8;
#pragma unroll
        for (int nt = 0; nt < 4; nt++) {
            int lc = wc * 32 + nt * 8 + tig * 2;
            if (r1 < NN) out[(size_t)r1 * 128 + (lc >> 1)] = h2u(c[mt][nt][0], c[mt][nt][1]);
            if (r2 < NN) out[(size_t)r2 * 128 + (lc >> 1)] = h2u(c[mt][nt][2], c[mt][nt][3]);
        }
    }
}

// ---------------- FUSED edge kernel (f16, half P gather) ----------------
__global__ __launch_bounds__(512, 2)
void k_e2c(const int* __restrict__ src, const int* __restrict__ dst,
           const float* __restrict__ W1row, const float* __restrict__ b1,
           const float* __restrict__ b2, const float* __restrict__ bc1,
           const float* __restrict__ Wc2) {
    extern __shared__ uint32_t sm[];
    uint32_t* sm_ms = sm + U_MS;
    uint32_t* sm_as = sm + U_MS;
    uint32_t* sm_bs = sm + U_BS;
    float* s_wr  = (float*)(sm + U_WR);
    float* s_b1  = (float*)(sm + U_B1);
    float* s_b2  = (float*)(sm + U_B2);
    float* s_bc1 = (float*)(sm + U_BC1);
    float* s_w2  = (float*)(sm + U_W2);
    float* s_rad = (float*)(sm + U_RAD);
    float* s_red = (float*)(sm + U_RED);
    int*   s_src = (int*)(sm + U_SRC);
    int*   s_dst = (int*)(sm + U_DST);

    const int tid = threadIdx.x;
    const int row0 = blockIdx.x * 64;
    if (tid < 64) {
        int e = row0 + tid;
        s_src[tid] = src[e];
        s_dst[tid] = dst[e];
        s_rad[tid] = g_xdiff[e * 4 + 3];
        s_red[tid] = 0.0f;
    }
    if (tid < HIDF) {
        s_wr[tid] = W1row[tid];
        s_b1[tid] = b1[tid];
        s_b2[tid] = b2[tid];
        s_bc1[tid] = bc1[tid];
        s_w2[tid] = Wc2[tid];
    }
    __syncthreads();
    const uint32_t bs_base = (uint32_t)__cvta_generic_to_shared(sm_bs);
    const int lane = tid & 31;
    const int g = lane >> 2;
    const int tig = lane & 3;
    const int wid = tid >> 5;
    const int wr = wid >> 3;
    const int wc = wid & 7;
    float c[2][4][4];
#pragma unroll
    for (int mt = 0; mt < 2; mt++)
#pragma unroll
        for (int nt = 0; nt < 4; nt++)
#pragma unroll
            for (int q = 0; q < 4; q++) c[mt][nt][q] = 0.0f;

#define ISSUE_B(WTH, KB, BUF)                                                    \
    {                                                                            \
        _Pragma("unroll")                                                        \
        for (int i = 0; i < 4; i++) {                                            \
            int f = tid + i * 512;                                               \
            int n = f >> 3;                                                      \
            int j = (f & 7) << 2;                                                \
            cp16(bs_base + (uint32_t)(((BUF) * 256 + n) * BS_STR + j) * 4,       \
                 (WTH) + (size_t)n * 128 + (KB) * 32 + j);                       \
        }                                                                        \
    }

    // ================= phase 1 =================
    ISSUE_B(g_wth_e2, 0, 0);
    CP_COMMIT();
    for (int kb = 0; kb < 4; kb++) {
        const int buf = kb & 1;
        // A staging: 64 rows x 32 u32; thread -> 4 u32 (8 halves) from half P
        {
            int r = tid >> 3;
            int k4 = (tid & 7) << 2;         // u32 offset in chunk
            int kg = kb * 64 + (k4 << 1);    // half index
            uint4 ua = *(const uint4*)(g_pah + (size_t)s_src[r] * 128 + kb * 32 + k4);
            uint4 ub = *(const uint4*)(g_pbh + (size_t)s_dst[r] * 128 + kb * 32 + k4);
            float rad = s_rad[r];
            float2 a0 = u2f2(ua.x), a1 = u2f2(ua.y), a2 = u2f2(ua.z), a3 = u2f2(ua.w);
            float2 q0 = u2f2(ub.x), q1 = u2f2(ub.y), q2 = u2f2(ub.z), q3 = u2f2(ub.w);
            float v0 = silu_f(a0.x + q0.x + rad * s_wr[kg + 0] + s_b1[kg + 0]);
            float v1 = silu_f(a0.y + q0.y + rad * s_wr[kg + 1] + s_b1[kg + 1]);
            float v2 = silu_f(a1.x + q1.x + rad * s_wr[kg + 2] + s_b1[kg + 2]);
            float v3 = silu_f(a1.y + q1.y + rad * s_wr[kg + 3] + s_b1[kg + 3]);
            float v4 = silu_f(a2.x + q2.x + rad * s_wr[kg + 4] + s_b1[kg + 4]);
            float v5 = silu_f(a2.y + q2.y + rad * s_wr[kg + 5] + s_b1[kg + 5]);
            float v6 = silu_f(a3.x + q3.x + rad * s_wr[kg + 6] + s_b1[kg + 6]);
            float v7 = silu_f(a3.y + q3.y + rad * s_wr[kg + 7] + s_b1[kg + 7]);
            uint4 o;
            o.x = h2u(v0, v1); o.y = h2u(v2, v3);
            o.z = h2u(v4, v5); o.w = h2u(v6, v7);
            *(uint4*)&sm_as[r * AS_STR + k4] = o;
        }
        if (kb + 1 < 4) {
            ISSUE_B(g_wth_e2, kb + 1, buf ^ 1);
            CP_COMMIT();
            cp_wait<1>();
        } else {
            cp_wait<0>();
        }
        __syncthreads();
#pragma unroll
        for (int ks = 0; ks < 4; ks++) {
            const int kb2 = ks * 8;
            uint32_t af[2][4], bf[4][2];
#pragma unroll
            for (int mt = 0; mt < 2; mt++) {
                int rb = wr * 32 + mt * 16;
                af[mt][0] = sm_as[(rb + g) * AS_STR + kb2 + tig];
                af[mt][1] = sm_as[(rb + g + 8) * AS_STR + kb2 + tig];
                af[mt][2] = sm_as[(rb + g) * AS_STR + kb2 + tig + 4];
                af[mt][3] = sm_as[(rb + g + 8) * AS_STR + kb2 + tig + 4];
            }
#pragma unroll
            for (int nt = 0; nt < 4; nt++) {
                int cb = wc * 32 + nt * 8;
                bf[nt][0] = sm_bs[(buf * 256 + cb + g) * BS_STR + kb2 + tig];
                bf[nt][1] = sm_bs[(buf * 256 + cb + g) * BS_STR + kb2 + tig + 4];
            }
#pragma unroll
            for (int mt = 0; mt < 2; mt++)
#pragma unroll
                for (int nt = 0; nt < 4; nt++)
                    mma_f16(c[mt][nt], af[mt], bf[nt]);
        }
        __syncthreads();
    }
    // ---- epilogue 1 ----
#pragma unroll
    for (int mt = 0; mt < 2; mt++) {
        int r1 = wr * 32 + mt * 16 + g;
        int r2 = r1 + 8;
        int d1 = s_dst[r1], d2 = s_dst[r2];
#pragma unroll
        for (int nt = 0; nt < 4; nt++) {
            int lc = wc * 32 + nt * 8 + tig * 2;
            float v0 = silu_f(c[mt][nt][0] + s_b2[lc]);
            float v1 = silu_f(c[mt][nt][1] + s_b2[lc + 1]);
            float v2 = silu_f(c[mt][nt][2] + s_b2[lc]);
            float v3 = silu_f(c[mt][nt][3] + s_b2[lc + 1]);
            sm_ms[r1 * MS_STR + (lc >> 1)] = h2u(v0, v1);
            sm_ms[r2 * MS_STR + (lc >> 1)] = h2u(v2, v3);
            red_v2(g_hneigh + (size_t)d1 * HIDF + lc, v0, v1);
            red_v2(g_hneigh + (size_t)d2 * HIDF + lc, v2, v3);
        }
    }
    __syncthreads();

    // ================= phase 2 =================
#pragma unroll
    for (int mt = 0; mt < 2; mt++)
#pragma unroll
        for (int nt = 0; nt < 4; nt++)
#pragma unroll
            for (int q = 0; q < 4; q++) c[mt][nt][q] = 0.0f;

    ISSUE_B(g_wth_c1, 0, 0);
    CP_COMMIT();
    for (int kb = 0; kb < 4; kb++) {
        const int buf = kb & 1;
        if (kb + 1 < 4) {
            ISSUE_B(g_wth_c1, kb + 1, buf ^ 1);
            CP_COMMIT();
            cp_wait<1>();
        } else {
            cp_wait<0>();
        }
        __syncthreads();
#pragma unroll
        for (int ks = 0; ks < 4; ks++) {
            const int ku = kb * 32 + ks * 8;
            const int kb2 = ks * 8;
            uint32_t af[2][4], bf[4][2];
#pragma unroll
            for (int mt = 0; mt < 2; mt++) {
                int rb = wr * 32 + mt * 16;
                af[mt][0] = sm_ms[(rb + g) * MS_STR + ku + tig];
                af[mt][1] = sm_ms[(rb + g + 8) * MS_STR + ku + tig];
                af[mt][2] = sm_ms[(rb + g) * MS_STR + ku + tig + 4];
                af[mt][3] = sm_ms[(rb + g + 8) * MS_STR + ku + tig + 4];
            }
#pragma unroll
            for (int nt = 0; nt < 4; nt++) {
                int cb = wc * 32 + nt * 8;
                bf[nt][0] = sm_bs[(buf * 256 + cb + g) * BS_STR + kb2 + tig];
                bf[nt][1] = sm_bs[(buf * 256 + cb + g) * BS_STR + kb2 + tig + 4];
            }
#pragma unroll
            for (int mt = 0; mt < 2; mt++)
#pragma unroll
                for (int nt = 0; nt < 4; nt++)
                    mma_f16(c[mt][nt], af[mt], bf[nt]);
        }
        __syncthreads();
    }
    // ---- epilogue 2 ----
#pragma unroll
    for (int mt = 0; mt < 2; mt++) {
        float s1 = 0.0f, s2 = 0.0f;
#pragma unroll
        for (int nt = 0; nt < 4; nt++) {
            int lc = wc * 32 + nt * 8 + tig * 2;
            s1 += silu_f(c[mt][nt][0] + s_bc1[lc]) * s_w2[lc]
                + silu_f(c[mt][nt][1] + s_bc1[lc + 1]) * s_w2[lc + 1];
            s2 += silu_f(c[mt][nt][2] + s_bc1[lc]) * s_w2[lc]
                + silu_f(c[mt][nt][3] + s_bc1[lc + 1]) * s_w2[lc + 1];
        }
        s1 += __shfl_xor_sync(0xffffffffu, s1, 1);
        s1 += __shfl_xor_sync(0xffffffffu, s1, 2);
        s2 += __shfl_xor_sync(0xffffffffu, s2, 1);
        s2 += __shfl_xor_sync(0xffffffffu, s2, 2);
        if (tig == 0) {
            atomicAdd(&s_red[wr * 32 + mt * 16 + g], s1);
            atomicAdd(&s_red[wr * 32 + mt * 16 + g + 8], s2);
        }
    }
    __syncthreads();
    if (tid < 64) {
        int e = row0 + tid;
        float s = s_red[tid];
        float4 xd = *(const float4*)(g_xdiff + (size_t)e * 4);
        int d = s_dst[tid];
        atomicAdd(&g_xsum[d * 3 + 0], s * xd.x);
        atomicAdd(&g_xsum[d * 3 + 1], s * xd.y);
        atomicAdd(&g_xsum[d * 3 + 2], s * xd.z);
    }
#undef ISSUE_B
}

// ---------------- node GEMM 1 (f16): hn1 = silu([nf, h_neigh] @ W_n1 + b) ----------------
__global__ __launch_bounds__(512, 2)
void k_n1_f16(const float* __restrict__ nf, const float* __restrict__ b) {
    extern __shared__ uint32_t sm[];
    uint32_t* As = sm + N1_U_AS;    // 64 x AS_STR
    uint32_t* Bs = sm + N1_U_BS;    // 2 x 256 x AS_STR
    float* s_b = (float*)(sm + N1_U_B);
    const int tid = threadIdx.x;
    const int row0 = blockIdx.x * 64;
    if (tid < HIDF) s_b[tid] = b[tid];
    __syncthreads();
    const uint32_t bs_base = (uint32_t)__cvta_generic_to_shared(Bs);
    const int lane = tid & 31;
    const int g = lane >> 2;
    const int tig = lane & 3;
    const int wid = tid >> 5;
    const int wr = wid >> 3;
    const int wc = wid & 7;
    float c[2][4][4];
#pragma unroll
    for (int mt = 0; mt < 2; mt++)
#pragma unroll
        for (int nt = 0; nt < 4; nt++)
#pragma unroll
            for (int q = 0; q < 4; q++) c[mt][nt][q] = 0.0f;

#define ISSUE_BN(KB, BUF)                                                        \
    {                                                                            \
        _Pragma("unroll")                                                        \
        for (int i = 0; i < 4; i++) {                                            \
            int f = tid + i * 512;                                               \
            int n = f >> 3;                                                      \
            int j = (f & 7) << 2;                                                \
            cp16(bs_base + (uint32_t)(((BUF) * 256 + n) * BS_STR + j) * 4,       \
                 g_wth_n1 + (size_t)n * 192 + (KB) * 32 + j);                    \
        }                                                                        \
    }

    ISSUE_BN(0, 0);
    CP_COMMIT();
    for (int kb = 0; kb < 6; kb++) {   // K=384, chunks of 64
        const int buf = kb & 1;
        // A staging: 64 x 32 u32; thread -> 4 u32 (8 floats -> halves)
        {
            int r = tid >> 3;
            int k4 = (tid & 7) << 2;
            int kg = kb * 64 + (k4 << 1);
            int rr = min(row0 + r, NN - 1);
            const float* base = (kg < INF) ? (nf + (size_t)rr * INF + kg)
                                           : (g_hneigh + (size_t)rr * HIDF + (kg - INF));
            float4 f0 = *(const float4*)(base);
            float4 f1 = *(const float4*)(base + 4);
            uint4 o;
            o.x = h2u(f0.x, f0.y); o.y = h2u(f0.z, f0.w);
            o.z = h2u(f1.x, f1.y); o.w = h2u(f1.z, f1.w);
            *(uint4*)&As[r * AS_STR + k4] = o;
        }
        if (kb + 1 < 6) {
            ISSUE_BN(kb + 1, buf ^ 1);
            CP_COMMIT();
            cp_wait<1>();
        } else {
            cp_wait<0>();
        }
        __syncthreads();
#pragma unroll
        for (int ks = 0; ks < 4; ks++) {
            const int kb2 = ks * 8;
            uint32_t af[2][4], bf[4][2];
#pragma unroll
            for (int mt = 0; mt < 2; mt++) {
                int rb = wr * 32 + mt * 16;
                af[mt][0] = As[(rb + g) * AS_STR + kb2 + tig];
                af[mt][1] = As[(rb + g + 8) * AS_STR + kb2 + tig];
                af[mt][2] = As[(rb + g) * AS_STR + kb2 + tig + 4];
                af[mt][3] = As[(rb + g + 8) * AS_STR + kb2 + tig + 4];
            }
#pragma unroll
            for (int nt = 0; nt < 4; nt++) {
                int cb = wc * 32 + nt * 8;
                bf[nt][0] = Bs[(buf * 256 + cb + g) * BS_STR + kb2 + tig];
                bf[nt][1] = Bs[(buf * 256 + cb + g) * BS_STR + kb2 + tig + 4];
            }
#pragma unroll
            for (int mt = 0; mt < 2; mt++)
#pragma unroll
                for (int nt = 0; nt < 4; nt++)
                    mma_f16(c[mt][nt], af[mt], bf[nt]);
        }
        __syncthreads();
    }
#pragma unroll
    for (int mt = 0; mt < 2; mt++) {
        int r1 = row0 + wr * 32 + mt * 16 + g;
        int r2 = r1 + 8;
#pragma unroll
        for (int nt = 0; nt < 4; nt++) {
            int lc = wc * 32 + nt * 8 + tig * 2;
            if (r1 < NN)
                *(float2*)(g_hn1 + (size_t)r1 * HIDF + lc) =
                    make_float2(silu_f(c[mt][nt][0] + s_b[lc]),
                                silu_f(c[mt][nt][1] + s_b[lc + 1]));
            if (r2 < NN)
                *(float2*)(g_hn1 + (size_t)r2 * HIDF + lc) =
                    make_float2(silu_f(c[mt][nt][2] + s_b[lc]),
                                silu_f(c[mt][nt][3] + s_b[lc + 1]));
        }
    }
#undef ISSUE_BN
}

// ---------------- node GEMM 2 + BN stats (fp32) ----------------
__global__ __launch_bounds__(256, 2)
void k_n2(const float* __restrict__ W, const float* __restrict__ b,
          float* __restrict__ out) {
    __shared__ float As[TBK][128 + 4];
    __shared__ float Bs[TBK][128 + 4];
    __shared__ float csum[128];
    __shared__ float csq[128];
    const int tid = threadIdx.x;
    const int row0 = blockIdx.x * 128;
    if (tid < 128) { csum[tid] = 0.0f; csq[tid] = 0.0f; }
    const int tx = tid & 15;
    const int ty = tid >> 4;
    u64 acc2[8][4];
#pragma unroll
    for (int i = 0; i < 8; i++)
#pragma unroll
        for (int j = 0; j < 4; j++) acc2[i][j] = 0ull;

    for (int kt = 0; kt < HIDF / TBK; kt++) {
#pragma unroll
        for (int i = 0; i < 2; i++) {
            int f = tid + i * 256;
            int r = f >> 2;
            int kk = (f & 3) << 2;
            int rr = min(row0 + r, NN - 1);
            float4 v = *(const float4*)(g_hn1 + (size_t)rr * HIDF + kt * TBK + kk);
            As[kk + 0][r] = v.x; As[kk + 1][r] = v.y;
            As[kk + 2][r] = v.z; As[kk + 3][r] = v.w;
        }
#pragma unroll
        for (int i = 0; i < 2; i++) {
            int f = tid + i * 256;
            int kk = f >> 5;
            int c = (f & 31) << 2;
            *(float4*)&Bs[kk][c] =
                *(const float4*)(W + (size_t)(kt * TBK + kk) * OUTF + c);
        }
        __syncthreads();
#pragma unroll
        for (int k = 0; k < TBK; k++)
            mt_step(acc2, &As[k][0], &Bs[k][0], ty * 8, tx * 8);
        __syncthreads();
    }
    float bb[8];
#pragma unroll
    for (int j = 0; j < 8; j++) bb[j] = b[tx * 8 + j];
    float cs[8], cq[8];
#pragma unroll
    for (int j = 0; j < 8; j++) { cs[j] = 0.0f; cq[j] = 0.0f; }
#pragma unroll
    for (int i = 0; i < 8; i++) {
        int row = row0 + ty * 8 + i;
        if (row < NN) {
            float a[8], h[8];
#pragma unroll
            for (int jp = 0; jp < 4; jp++) upk2(acc2[i][jp], a[2 * jp], a[2 * jp + 1]);
#pragma unroll
            for (int j = 0; j < 8; j++) {
                h[j] = a[j] + bb[j];
                cs[j] += h[j];
                cq[j] += h[j] * h[j];
            }
            *(float4*)(out + (size_t)row * OUTF + tx * 8) =
                make_float4(h[0], h[1], h[2], h[3]);
            *(float4*)(out + (size_t)row * OUTF + tx * 8 + 4) =
                make_float4(h[4], h[5], h[6], h[7]);
        }
    }
#pragma unroll
    for (int j = 0; j < 8; j++) {
        atomicAdd(&csum[tx * 8 + j], cs[j]);
        atomicAdd(&csq[tx * 8 + j], cq[j]);
    }
    __syncthreads();
    if (tid < 128) {
        atomicAdd(&g_colsum[tid], csum[tid]);
        atomicAdd(&g_colsq[tid], csq[tid]);
    }
}

// ---------------- x output ----------------
__global__ void k_xout(const float* __restrict__ coord, float* __restrict__ out) {
    int n = blockIdx.x * blockDim.x + threadIdx.x;
    if (n >= NN) return;
    float inv = 1.0f / fmaxf(g_deg[n], 1.0f);
    float* o = out + (size_t)NN * OUTF + n * 3;
    o[0] = coord[n * 3 + 0] + g_xsum[n * 3 + 0] * inv;
    o[1] = coord[n * 3 + 1] + g_xsum[n * 3 + 1] * inv;
    o[2] = coord[n * 3 + 2] + g_xsum[n * 3 + 2] * inv;
}

// ---------------- BatchNorm finalize ----------------
__global__ void k_bn(const float* __restrict__ gamma, const float* __restrict__ beta,
                     float* __restrict__ out) {
    int idx = blockIdx.x * blockDim.x + threadIdx.x;
    if (idx >= NN * OUTF) return;
    int c = idx & (OUTF - 1);
    const float invN = 1.0f / (float)NN;
    float mu = g_colsum[c] * invN;
    float var = g_colsq[c] * invN - mu * mu;
    float h = out[idx];
    out[idx] = (h - mu) * rsqrtf(var + 1e-5f) * gamma[c] + beta[c];
}

// ---------------- launch ----------------
extern "C" void kernel_launch(void* const* d_in, const int* in_sizes, int n_in,
                              void* d_out, int out_size) {
    const float* nf    = (const float*)d_in[0];
    const float* coord = (const float*)d_in[1];
    const int*   src   = (const int*)d_in[2];
    const int*   dst   = (const int*)d_in[3];
    const float* We1   = (const float*)d_in[4];
    const float* be1   = (const float*)d_in[5];
    const float* We2   = (const float*)d_in[6];
    const float* be2   = (const float*)d_in[7];
    const float* Wc1   = (const float*)d_in[8];
    const float* bc1   = (const float*)d_in[9];
    const float* Wc2   = (const float*)d_in[10];
    const float* Wn1   = (const float*)d_in[11];
    const float* bn1   = (const float*)d_in[12];
    const float* Wn2   = (const float*)d_in[13];
    const float* bn2   = (const float*)d_in[14];
    const float* gamma = (const float*)d_in[15];
    const float* beta  = (const float*)d_in[16];
    float* out = (float*)d_out;

    cudaFuncSetAttribute(k_e2c, cudaFuncAttributeMaxDynamicSharedMemorySize, E2C_SMEM_BYTES);
    cudaFuncSetAttribute(k_pre_f16, cudaFuncAttributeMaxDynamicSharedMemorySize, PRE_SMEM_BYTES);
    cudaFuncSetAttribute(k_n1_f16, cudaFuncAttributeMaxDynamicSharedMemorySize, N1_SMEM_BYTES);

    void* p;
    cudaGetSymbolAddress(&p, g_hneigh);
    cudaMemsetAsync(p, 0, sizeof(float) * (size_t)NN * HIDF);
    cudaGetSymbolAddress(&p, g_xsum);
    cudaMemsetAsync(p, 0, sizeof(float) * NN * 3);
    cudaGetSymbolAddress(&p, g_deg);
    cudaMemsetAsync(p, 0, sizeof(float) * NN);
    cudaGetSymbolAddress(&p, g_colsum);
    cudaMemsetAsync(p, 0, sizeof(float) * OUTF);
    cudaGetSymbolAddress(&p, g_colsq);
    cudaMemsetAsync(p, 0, sizeof(float) * OUTF);

    k_wprep<<<(KN1 * HIDF + 255) / 256, 256>>>(We1, We2, Wc1, Wn1);
    k_geom<<<(NE + 255) / 256, 256>>>(coord, src, dst);

    dim3 gp((NN + 63) / 64, 2);
    k_pre_f16<<<gp, 512, PRE_SMEM_BYTES>>>(nf);

    k_e2c<<<NE / 64, 512, E2C_SMEM_BYTES>>>(src, dst, We1 + (size_t)2 * INF * HIDF,
                                            be1, be2, bc1, Wc2);

    k_n1_f16<<<(NN + 63) / 64, 512, N1_SMEM_BYTES>>>(nf, bn1);
    k_n2<<<(NN + 127) / 128, 256>>>(Wn2, bn2, out);

    k_xout<<<(NN + 255) / 256, 256>>>(coord, out);
    k_bn<<<(NN * OUTF + 255) / 256, 256>>>(gamma, beta, out);
}